// round 10
// baseline (speedup 1.0000x reference)
#include <cuda_runtime.h>

#define Nn 65536
#define Ee 2097152
#define Bb 1024
#define FXDIM 78
#define DIM 32
#define EMBD 128
#define VOCAB 26
#define PLENN 1000
#define KSZ 8
#define CLENN 121
#define NFIL 32
#define ADIM 6656   /* VOCAB * NFIL * KSZ */
#define A4 1664     /* ADIM/4 */
#define OUTDIM 128

// ---------------- scratch (device globals; no allocations) ----------------
__device__ __align__(16) float g_p[Nn * DIM];
__device__ __align__(16) float g_y[Nn * DIM];
__device__ float g_stats[5 * 64];
__device__ float g_hg[Bb * DIM];
__device__ __align__(16) float g_xc[Bb * 256];    // [xd | xt]
__device__ __align__(16) float g_f1[Bb * 1024];
__device__ __align__(16) float g_Wt[PLENN * 256]; // conv_w transposed to [p][f*8+k]
__device__ __align__(16) float g_A[Bb * ADIM];
__device__ __align__(16) float g_U[ADIM * OUTDIM];
__device__ __align__(16) float g_bias2[OUTDIM];
__device__ __align__(16) float g_part[16 * 1024 * 128];   // split-K partials (8 MB)
// CSR scratch
__device__ __align__(16) int g_off[Nn + 4];
__device__ __align__(16) int g_pos[Nn];
__device__ __align__(16) int g_srcl[Ee];

__device__ __forceinline__ void f4add(float4& a, const float4& b) {
    a.x += b.x; a.y += b.y; a.z += b.z; a.w += b.w;
}

// ---------------- init ----------------
__global__ void k_init() {
    int i = blockIdx.x * 256 + threadIdx.x;   // 65536 threads
    if (i < Nn) g_pos[i] = 0;
    if (i < Bb * DIM) g_hg[i] = 0.f;
    if (i < 5 * 64) g_stats[i] = 0.f;
    if (i < OUTDIM) g_bias2[i] = 0.f;
}

// ---------------- CSR build (vectorized) ----------------
__global__ void k_hist(const int* __restrict__ ei) {
    int e4 = blockIdx.x * 256 + threadIdx.x;
    int4 d = ((const int4*)(ei + Ee))[e4];
    atomicAdd(&g_pos[d.x], 1);
    atomicAdd(&g_pos[d.y], 1);
    atomicAdd(&g_pos[d.z], 1);
    atomicAdd(&g_pos[d.w], 1);
}

__global__ void k_scan() {  // 1 block, 1024 threads, 64 elems each
    int t = threadIdx.x, lane = t & 31, wid = t >> 5;
    __shared__ int ws[32];
    const int4* pos4 = (const int4*)g_pos;
    int base4 = t * 16;
    int s = 0;
#pragma unroll
    for (int j = 0; j < 16; j++) {
        int4 v = pos4[base4 + j];
        s += v.x + v.y + v.z + v.w;
    }
    int v = s;
#pragma unroll
    for (int off = 1; off < 32; off <<= 1) {
        int u = __shfl_up_sync(0xffffffffu, v, off);
        if (lane >= off) v += u;
    }
    if (lane == 31) ws[wid] = v;
    __syncthreads();
    if (wid == 0) {
        int w = ws[lane];
#pragma unroll
        for (int off = 1; off < 32; off <<= 1) {
            int u = __shfl_up_sync(0xffffffffu, w, off);
            if (lane >= off) w += u;
        }
        ws[lane] = w;
    }
    __syncthreads();
    int run = v - s + (wid ? ws[wid - 1] : 0);
    int4* off4 = (int4*)g_off;
    int4* posw4 = (int4*)g_pos;
#pragma unroll
    for (int j = 0; j < 16; j++) {
        int4 d = pos4[base4 + j];
        int4 o;
        o.x = run;
        o.y = run + d.x;
        o.z = o.y + d.y;
        o.w = o.z + d.z;
        off4[base4 + j] = o;
        posw4[base4 + j] = o;
        run = o.w + d.w;
    }
    if (t == 1023) g_off[Nn] = run;
}

__global__ void k_fill(const int* __restrict__ ei) {
    int e4 = blockIdx.x * 256 + threadIdx.x;
    int4 sv = ((const int4*)ei)[e4];
    int4 dv = ((const int4*)(ei + Ee))[e4];
    int s0 = atomicAdd(&g_pos[dv.x], 1); g_srcl[s0] = sv.x;
    int s1 = atomicAdd(&g_pos[dv.y], 1); g_srcl[s1] = sv.y;
    int s2 = atomicAdd(&g_pos[dv.z], 1); g_srcl[s2] = sv.z;
    int s3 = atomicAdd(&g_pos[dv.w], 1); g_srcl[s3] = sv.w;
}

// ---------------- protein branch ----------------
__global__ void k_transpose(const float* __restrict__ conv_w) {
    int f = blockIdx.x;
    for (int i = threadIdx.x; i < PLENN * KSZ; i += 256) {
        int p = i >> 3, k = i & 7;
        g_Wt[p * 256 + f * 8 + k] = conv_w[f * PLENN * KSZ + i];
    }
}

// 4 proteins per block; 64 threads per protein, float4 smem RMW
__global__ void k_buildA4(const int* __restrict__ target) {
    extern __shared__ float4 sA4[];
    int tid = threadIdx.x;
    int b0 = blockIdx.x * 4;
    int pg = tid >> 6;          // protein slot 0..3
    int col4 = tid & 63;        // float4 column
    for (int i = tid; i < 4 * A4; i += 256) sA4[i] = make_float4(0.f, 0.f, 0.f, 0.f);
    __syncthreads();
    const float4* Wt4 = (const float4*)g_Wt;
    const int* tp = target + (b0 + pg) * PLENN;
    int pbase = pg * A4;
    for (int p = 0; p < PLENN; p += 2) {
        int va = tp[p], vb = tp[p + 1];
        float4 w0 = Wt4[p * 64 + col4];
        float4 w1 = Wt4[(p + 1) * 64 + col4];
        int ia = pbase + va * 64 + col4;
        float4 Aa = sA4[ia]; f4add(Aa, w0); sA4[ia] = Aa;
        int ib = pbase + vb * 64 + col4;
        float4 Ab = sA4[ib]; f4add(Ab, w1); sA4[ib] = Ab;
    }
    __syncthreads();
    float4* gA4 = (float4*)g_A;
    for (int j = 0; j < 4; j++)
        for (int i = tid; i < A4; i += 256)
            gA4[(b0 + j) * A4 + i] = sA4[j * A4 + i];
}

// U[(v*256+f*8+k)*128+o] = sum_t emb[v*128+t+k] * w_fcxt[(f*121+t)*128+o]
__global__ void k_buildU(const float* __restrict__ emb, const float* __restrict__ wfcxt) {
    __shared__ float se[EMBD];
    int f = blockIdx.x, v = blockIdx.y, o = threadIdx.x;
    se[o] = emb[v * EMBD + o];
    __syncthreads();
    float acc[KSZ];
#pragma unroll
    for (int k = 0; k < KSZ; k++) acc[k] = 0.f;
    const float* wf = wfcxt + f * CLENN * OUTDIM + o;
#pragma unroll 4
    for (int t = 0; t < CLENN; t++) {
        float wv = wf[t * OUTDIM];
#pragma unroll
        for (int k = 0; k < KSZ; k++) acc[k] += se[t + k] * wv;
    }
#pragma unroll
    for (int k = 0; k < KSZ; k++)
        g_U[(v * 256 + f * 8 + k) * OUTDIM + o] = acc[k];
}

__global__ void k_bias2(const float* __restrict__ wfcxt, const float* __restrict__ conv_b) {
    int f = blockIdx.x, o = threadIdx.x; // 128 threads
    float s = 0.f;
    for (int t = 0; t < CLENN; t++) s += wfcxt[(f * CLENN + t) * OUTDIM + o];
    atomicAdd(&g_bias2[o], s * conv_b[f]);
}

// ---------------- GIN layers ----------------
__global__ void k_proj78(const float* __restrict__ x, const float* __restrict__ W) {
    __shared__ float xs[64][80];
    __shared__ float ws[78][33];
    int tid = threadIdx.x;
    int row0 = blockIdx.x * 64;
    const float* xb = x + row0 * FXDIM;
    for (int i = tid; i < 64 * FXDIM; i += 256) xs[i / FXDIM][i % FXDIM] = xb[i];
    for (int i = tid; i < FXDIM * 32; i += 256) ws[i >> 5][i & 31] = W[i];
    __syncthreads();
    int c = tid & 31, w = tid >> 5;
    float acc[8];
#pragma unroll
    for (int j = 0; j < 8; j++) acc[j] = 0.f;
    for (int k = 0; k < FXDIM; k++) {
        float wv = ws[k][c];
#pragma unroll
        for (int j = 0; j < 8; j++) acc[j] += xs[w * 8 + j][k] * wv;
    }
#pragma unroll
    for (int j = 0; j < 8; j++) g_p[(row0 + w * 8 + j) * 32 + c] = acc[j];
}

// p = (y * s + t) @ W ; BN fold computed inline from stats slot
__global__ void k_proj32(int slot, const float* __restrict__ gamma,
                         const float* __restrict__ beta, const float* __restrict__ W) {
    __shared__ float xs[64][33];
    __shared__ float ws[32][33];
    __shared__ float sa[64];
    int tid = threadIdx.x;
    int row0 = blockIdx.x * 64;
    if (tid < 32) {
        float m = g_stats[slot * 64 + tid] * (1.f / Nn);
        float v = g_stats[slot * 64 + 32 + tid] * (1.f / Nn) - m * m;
        float s = gamma[tid] * rsqrtf(v + 1e-5f);
        sa[tid] = s;
        sa[32 + tid] = beta[tid] - m * s;
    }
    __syncthreads();
    const float4* y4 = (const float4*)g_y;
    for (int i = tid; i < 512; i += 256) {
        int r = i >> 3, q = i & 7;
        float4 v = y4[(row0 + r) * 8 + q];
        xs[r][q * 4 + 0] = v.x * sa[q * 4 + 0] + sa[32 + q * 4 + 0];
        xs[r][q * 4 + 1] = v.y * sa[q * 4 + 1] + sa[32 + q * 4 + 1];
        xs[r][q * 4 + 2] = v.z * sa[q * 4 + 2] + sa[32 + q * 4 + 2];
        xs[r][q * 4 + 3] = v.w * sa[q * 4 + 3] + sa[32 + q * 4 + 3];
    }
    for (int i = tid; i < 1024; i += 256) ws[i >> 5][i & 31] = W[i];
    __syncthreads();
    int c = tid & 31, w = tid >> 5;
    float acc[8];
#pragma unroll
    for (int j = 0; j < 8; j++) acc[j] = 0.f;
#pragma unroll
    for (int k = 0; k < 32; k++) {
        float wv = ws[k][c];
#pragma unroll
        for (int j = 0; j < 8; j++) acc[j] += xs[w * 8 + j][k] * wv;
    }
#pragma unroll
    for (int j = 0; j < 8; j++) g_p[(row0 + w * 8 + j) * 32 + c] = acc[j];
}

// fused: CSR gather (512 threads: 16 gather warps, 4 nodes each) + MLP + ReLU + BN stats
__global__ void __launch_bounds__(512) k_mlp(int layer, const float* __restrict__ ba,
                                             const float* __restrict__ Wb,
                                             const float* __restrict__ bb) {
    __shared__ float us[64][33];
    __shared__ float ws[32][33];
    __shared__ float r1[8][32];
    __shared__ float r2[8][32];
    __shared__ float bsh[32], bbsh[32];
    int tid = threadIdx.x;
    int lane = tid & 31, wid = tid >> 5;   // wid 0..15
    int row0 = blockIdx.x * 64;
    if (tid < 32) { bsh[tid] = ba[tid]; bbsh[tid] = bb[tid]; }
    for (int i = tid; i < 1024; i += 512) ws[i >> 5][i & 31] = Wb[i];
    __syncthreads();
    const float4* p4 = (const float4*)g_p;
    int eg = lane >> 3;   // edge slot 0..3
    int q = lane & 7;     // float4 chunk
    // 16 warps, 4 nodes each (2x gather concurrency vs 8-warp version)
    for (int nn = wid; nn < 64; nn += 16) {
        int node = row0 + nn;
        float4 a0 = make_float4(0.f, 0.f, 0.f, 0.f);
        float4 a1 = a0, a2 = a0, a3 = a0;
        if (eg == 0) a0 = p4[node * 8 + q];  // self term
        int i = g_off[node], ib = g_off[node + 1];
        for (; i + 16 <= ib; i += 16) {
            int s0 = g_srcl[i + eg];
            int s1 = g_srcl[i + 4 + eg];
            int s2 = g_srcl[i + 8 + eg];
            int s3 = g_srcl[i + 12 + eg];
            float4 v0 = p4[s0 * 8 + q];
            float4 v1 = p4[s1 * 8 + q];
            float4 v2 = p4[s2 * 8 + q];
            float4 v3 = p4[s3 * 8 + q];
            f4add(a0, v0);
            f4add(a1, v1);
            f4add(a2, v2);
            f4add(a3, v3);
        }
        for (; i + 4 <= ib; i += 4) f4add(a1, p4[g_srcl[i + eg] * 8 + q]);
        if (eg < ib - i) f4add(a2, p4[g_srcl[i + eg] * 8 + q]);
        f4add(a0, a1);
        f4add(a2, a3);
        f4add(a0, a2);
#pragma unroll
        for (int off = 8; off <= 16; off <<= 1) {
            a0.x += __shfl_xor_sync(0xffffffffu, a0.x, off);
            a0.y += __shfl_xor_sync(0xffffffffu, a0.y, off);
            a0.z += __shfl_xor_sync(0xffffffffu, a0.z, off);
            a0.w += __shfl_xor_sync(0xffffffffu, a0.w, off);
        }
        if (eg == 0) {
            us[nn][q * 4 + 0] = fmaxf(a0.x + bsh[q * 4 + 0], 0.f);
            us[nn][q * 4 + 1] = fmaxf(a0.y + bsh[q * 4 + 1], 0.f);
            us[nn][q * 4 + 2] = fmaxf(a0.z + bsh[q * 4 + 2], 0.f);
            us[nn][q * 4 + 3] = fmaxf(a0.w + bsh[q * 4 + 3], 0.f);
        }
    }
    __syncthreads();
    // MLP + output on warps 0..7 only
    if (wid < 8) {
        int c = lane, w = wid;
        float acc[8];
#pragma unroll
        for (int j = 0; j < 8; j++) acc[j] = bbsh[c];
#pragma unroll
        for (int k = 0; k < 32; k++) {
            float wv = ws[k][c];
#pragma unroll
            for (int j = 0; j < 8; j++) acc[j] += us[w * 8 + j][k] * wv;
        }
        float s1 = 0.f, s2 = 0.f;
#pragma unroll
        for (int j = 0; j < 8; j++) {
            float v = fmaxf(acc[j], 0.f);
            g_y[(row0 + w * 8 + j) * 32 + c] = v;
            s1 += v;
            s2 += v * v;
        }
        r1[w][c] = s1;
        r2[w][c] = s2;
    }
    __syncthreads();
    if (wid == 0) {
        int c = lane;
        float a = 0.f, b2 = 0.f;
#pragma unroll
        for (int qq = 0; qq < 8; qq++) { a += r1[qq][c]; b2 += r2[qq][c]; }
        atomicAdd(&g_stats[layer * 64 + c], a);
        atomicAdd(&g_stats[layer * 64 + 32 + c], b2);
    }
}

// global add pool: run-length accumulation + float4 reads, BN fold inline (slot 4)
__global__ void k_pool(const int* __restrict__ batch, const float* __restrict__ gamma,
                       const float* __restrict__ beta) {
    int tid = threadIdx.x;
    int lane = tid & 31;
    int gwarp = blockIdx.x * 8 + (tid >> 5);
    int q = lane & 7, sub = lane >> 3;
    int base = gwarp * 32;
    float s[4], t[4];
#pragma unroll
    for (int c = 0; c < 4; c++) {
        int d = q * 4 + c;
        float m = g_stats[4 * 64 + d] * (1.f / Nn);
        float vv = g_stats[4 * 64 + 32 + d] * (1.f / Nn) - m * m;
        s[c] = gamma[d] * rsqrtf(vv + 1e-5f);
        t[c] = beta[d] - m * s[c];
    }
    const float4* y4 = (const float4*)g_y;
    float4 acc = make_float4(0.f, 0.f, 0.f, 0.f);
    int cur = batch[base + sub];
#pragma unroll 2
    for (int j = 0; j < 8; j++) {
        int node = base + j * 4 + sub;
        int b = batch[node];
        float4 v = y4[node * 8 + q];
        v.x = v.x * s[0] + t[0];
        v.y = v.y * s[1] + t[1];
        v.z = v.z * s[2] + t[2];
        v.w = v.w * s[3] + t[3];
        if (b != cur) {
            atomicAdd(&g_hg[cur * 32 + q * 4 + 0], acc.x);
            atomicAdd(&g_hg[cur * 32 + q * 4 + 1], acc.y);
            atomicAdd(&g_hg[cur * 32 + q * 4 + 2], acc.z);
            atomicAdd(&g_hg[cur * 32 + q * 4 + 3], acc.w);
            acc = make_float4(0.f, 0.f, 0.f, 0.f);
            cur = b;
        }
        f4add(acc, v);
    }
    atomicAdd(&g_hg[cur * 32 + q * 4 + 0], acc.x);
    atomicAdd(&g_hg[cur * 32 + q * 4 + 1], acc.y);
    atomicAdd(&g_hg[cur * 32 + q * 4 + 2], acc.z);
    atomicAdd(&g_hg[cur * 32 + q * 4 + 3], acc.w);
}

// ---------------- high-efficiency SGEMM: BM=128, BK=16, 256 threads ----------------
template <int BN, int TN, bool PARTIAL, bool RELU>
__global__ void gemm128(const float* __restrict__ A, const float* __restrict__ W,
                        const float* __restrict__ bias, float* __restrict__ C,
                        int K, int ldc, int kChunk, float* __restrict__ part) {
    const int N = gridDim.y * BN;
    __shared__ float As[16][132];
    __shared__ float Ws[16][BN];
    int tid = threadIdx.x;
    int tx = tid & 15, ty = tid >> 4;
    int row0 = blockIdx.x * 128;
    int col0 = blockIdx.y * BN;
    int k0 = blockIdx.z * kChunk;
    int k1 = k0 + kChunk;
    if (k1 > K) k1 = K;
    float acc[8][TN];
#pragma unroll
    for (int i = 0; i < 8; i++)
#pragma unroll
        for (int j = 0; j < TN; j++) acc[i][j] = 0.f;

    int ar = tid >> 2;
    int ak = (tid & 3) * 4;
    int wr = tid >> 4;
    int wc = (tid & 15) * (BN / 16);

    for (int kb = k0; kb < k1; kb += 16) {
        const float* Ap = A + (row0 + ar) * K + kb + ak;
        float4 va = *(const float4*)Ap;
        float4 vb = *(const float4*)(Ap + 64 * K);
        As[ak + 0][ar] = va.x; As[ak + 1][ar] = va.y;
        As[ak + 2][ar] = va.z; As[ak + 3][ar] = va.w;
        As[ak + 0][ar + 64] = vb.x; As[ak + 1][ar + 64] = vb.y;
        As[ak + 2][ar + 64] = vb.z; As[ak + 3][ar + 64] = vb.w;
        const float* Wp = W + (kb + wr) * N + col0 + wc;
        if (BN == 128) {
            *(float4*)&Ws[wr][wc] = *(const float4*)Wp;
            *(float4*)&Ws[wr][wc + 4] = *(const float4*)(Wp + 4);
        } else {
            *(float4*)&Ws[wr][wc] = *(const float4*)Wp;
        }
        __syncthreads();
#pragma unroll
        for (int kk = 0; kk < 16; kk++) {
            float av[8], bv[TN];
            *(float4*)&av[0] = *(const float4*)&As[kk][ty * 8];
            *(float4*)&av[4] = *(const float4*)&As[kk][ty * 8 + 4];
            *(float4*)&bv[0] = *(const float4*)&Ws[kk][tx * 4];
            if (TN == 8) *(float4*)&bv[4] = *(const float4*)&Ws[kk][64 + tx * 4];
#pragma unroll
            for (int i = 0; i < 8; i++)
#pragma unroll
                for (int j = 0; j < TN; j++) acc[i][j] += av[i] * bv[j];
        }
        __syncthreads();
    }

    if (PARTIAL) {
        const int Mtot = gridDim.x * 128;
        float* P = part + (size_t)blockIdx.z * Mtot * N;
#pragma unroll
        for (int i = 0; i < 8; i++) {
            int r = row0 + ty * 8 + i;
            *(float4*)&P[r * N + col0 + tx * 4] = *(float4*)&acc[i][0];
            if (TN == 8)
                *(float4*)&P[r * N + col0 + 64 + tx * 4] = *(float4*)&acc[i][4];
        }
    } else {
#pragma unroll
        for (int i = 0; i < 8; i++) {
            int r = row0 + ty * 8 + i;
#pragma unroll
            for (int h = 0; h < TN / 4; h++) {
                int c = col0 + h * 64 + tx * 4;
                float4 v;
                v.x = acc[i][h * 4 + 0] + (bias ? bias[c + 0] : 0.f);
                v.y = acc[i][h * 4 + 1] + (bias ? bias[c + 1] : 0.f);
                v.z = acc[i][h * 4 + 2] + (bias ? bias[c + 2] : 0.f);
                v.w = acc[i][h * 4 + 3] + (bias ? bias[c + 3] : 0.f);
                if (RELU) {
                    v.x = fmaxf(v.x, 0.f); v.y = fmaxf(v.y, 0.f);
                    v.z = fmaxf(v.z, 0.f); v.w = fmaxf(v.w, 0.f);
                }
                *(float4*)&C[r * ldc + c] = v;
            }
        }
    }
}

// reduce xt partials (16 splits, 1024x128) into g_xc[:,128:256] with both biases
__global__ void k_reduce_xt(const float* __restrict__ b_fcxt) {
    int idx4 = blockIdx.x * 256 + threadIdx.x;   // 32768 float4s
    int i = idx4 * 4;
    int b = i >> 7, col = i & 127;
    const float4* P = (const float4*)g_part;
    float4 s = P[idx4];
#pragma unroll
    for (int k = 1; k < 16; k++) f4add(s, P[k * (Bb * 128 / 4) + idx4]);
    float4 bs = *(const float4*)&g_bias2[col];
    float4 bf = *(const float4*)&b_fcxt[col];
    s.x += bs.x + bf.x; s.y += bs.y + bf.y;
    s.z += bs.z + bf.z; s.w += bs.w + bf.w;
    *(float4*)&g_xc[b * 256 + 128 + col] = s;
}

// ---------------- small GEMM for xd (M=1024,K=32,N=128) ----------------
__global__ void gemm_xd(const float* __restrict__ A, const float* __restrict__ W,
                        const float* __restrict__ bias, float* __restrict__ C) {
    __shared__ float As[64][33];
    __shared__ float Ws[32][128];
    int tid = threadIdx.x;
    int row0 = blockIdx.x * 64;
    for (int i = tid; i < 64 * 32; i += 256) As[i >> 5][i & 31] = A[row0 * 32 + i];
    for (int i = tid; i < 32 * 128; i += 256) Ws[i >> 7][i & 127] = W[i];
    __syncthreads();
    int tx = tid & 31, ty = tid >> 5;
    float acc[8][4];
#pragma unroll
    for (int i = 0; i < 8; i++)
#pragma unroll
        for (int m = 0; m < 4; m++) acc[i][m] = 0.f;
#pragma unroll
    for (int k = 0; k < 32; k++) {
        float rw[4];
#pragma unroll
        for (int m = 0; m < 4; m++) rw[m] = Ws[k][tx + 32 * m];
#pragma unroll
        for (int i = 0; i < 8; i++) {
            float ra = As[ty * 8 + i][k];
#pragma unroll
            for (int m = 0; m < 4; m++) acc[i][m] += ra * rw[m];
        }
    }
#pragma unroll
    for (int i = 0; i < 8; i++) {
        int r = row0 + ty * 8 + i;
#pragma unroll
        for (int m = 0; m < 4; m++) {
            int c = tx + 32 * m;
            C[r * 256 + c] = fmaxf(acc[i][m] + bias[c], 0.f);
        }
    }
}

// ---------------- final head: reduce fc2 partials + bias + relu + dot w_out ----------------
__global__ void k_out(const float* __restrict__ b_fc2, const float* __restrict__ wout,
                      const float* __restrict__ bout, float* __restrict__ out) {
    int b = blockIdx.x, c = threadIdx.x; // 256 threads
    float s = g_part[b * 256 + c];
#pragma unroll
    for (int k = 1; k < 4; k++) s += g_part[k * (Bb * 256) + b * 256 + c];
    float v = fmaxf(s + b_fc2[c], 0.f) * wout[c];
#pragma unroll
    for (int off = 16; off; off >>= 1) v += __shfl_down_sync(0xffffffffu, v, off);
    __shared__ float ps[8];
    if ((c & 31) == 0) ps[c >> 5] = v;
    __syncthreads();
    if (c == 0) {
        float t = bout[0];
#pragma unroll
        for (int q = 0; q < 8; q++) t += ps[q];
        out[b] = t;
    }
}

// ---------------- launcher ----------------
extern "C" void kernel_launch(void* const* d_in, const int* in_sizes, int n_in,
                              void* d_out, int out_size) {
    const float* x = (const float*)d_in[0];
    const int* edge_index = (const int*)d_in[1];
    const int* batch = (const int*)d_in[2];
    const int* target = (const int*)d_in[3];
    const float* w1a = (const float*)d_in[4];
    const float* b1a = (const float*)d_in[5];
    const float* w1b = (const float*)d_in[6];
    const float* b1b = (const float*)d_in[7];
    const float* wa = (const float*)d_in[8];
    const float* ba = (const float*)d_in[9];
    const float* wb = (const float*)d_in[10];
    const float* bb = (const float*)d_in[11];
    const float* gamma = (const float*)d_in[12];
    const float* beta = (const float*)d_in[13];
    const float* w_fcxd = (const float*)d_in[14];
    const float* b_fcxd = (const float*)d_in[15];
    const float* emb = (const float*)d_in[16];
    const float* conv_w = (const float*)d_in[17];
    const float* conv_b = (const float*)d_in[18];
    const float* w_fcxt = (const float*)d_in[19];
    const float* b_fcxt = (const float*)d_in[20];
    const float* w_fc1 = (const float*)d_in[21];
    const float* b_fc1 = (const float*)d_in[22];
    const float* w_fc2 = (const float*)d_in[23];
    const float* b_fc2 = (const float*)d_in[24];
    const float* w_out = (const float*)d_in[25];
    const float* b_out = (const float*)d_in[26];
    float* out = (float*)d_out;

    float *hgP, *xcP, *f1P, *AP, *UP, *partP;
    cudaGetSymbolAddress((void**)&hgP, g_hg);
    cudaGetSymbolAddress((void**)&xcP, g_xc);
    cudaGetSymbolAddress((void**)&f1P, g_f1);
    cudaGetSymbolAddress((void**)&AP, g_A);
    cudaGetSymbolAddress((void**)&UP, g_U);
    cudaGetSymbolAddress((void**)&partP, g_part);

    cudaFuncSetAttribute(k_buildA4, cudaFuncAttributeMaxDynamicSharedMemorySize,
                         4 * ADIM * (int)sizeof(float));

    // one-time streams (fork-join capture pattern)
    static cudaStream_t s2 = 0, s3 = 0;
    static cudaEvent_t evF = 0, evJ = 0, evC = 0;
    static bool tried = false;
    static bool use2 = false;
    if (!tried) {
        tried = true;
        if (cudaStreamCreateWithFlags(&s2, cudaStreamNonBlocking) == cudaSuccess &&
            cudaStreamCreateWithFlags(&s3, cudaStreamNonBlocking) == cudaSuccess &&
            cudaEventCreateWithFlags(&evF, cudaEventDisableTiming) == cudaSuccess &&
            cudaEventCreateWithFlags(&evJ, cudaEventDisableTiming) == cudaSuccess &&
            cudaEventCreateWithFlags(&evC, cudaEventDisableTiming) == cudaSuccess) {
            use2 = true;
        }
    }
    cudaStream_t st2 = use2 ? s2 : (cudaStream_t)0;
    cudaStream_t st3 = use2 ? s3 : (cudaStream_t)0;

    k_init<<<256, 256>>>();

    if (use2) {
        cudaEventRecord(evF, 0);
        cudaStreamWaitEvent(st2, evF, 0);
        cudaStreamWaitEvent(st3, evF, 0);
    }

    // ---- stream 2: protein branch + xt GEMM ----
    k_transpose<<<NFIL, 256, 0, st2>>>(conv_w);
    k_buildA4<<<Bb / 4, 256, 4 * ADIM * sizeof(float), st2>>>(target);
    k_buildU<<<dim3(NFIL, VOCAB), 128, 0, st2>>>(emb, w_fcxt);
    k_bias2<<<NFIL, 128, 0, st2>>>(w_fcxt, conv_b);
    gemm128<128, 8, true, false><<<dim3(8, 1, 16), 256, 0, st2>>>(
        AP, UP, nullptr, nullptr, ADIM, 0, 416, partP);
    k_reduce_xt<<<128, 256, 0, st2>>>(b_fcxt);

    // ---- stream 3: CSR build (overlaps proj78) ----
    k_hist<<<Ee / 1024, 256, 0, st3>>>(edge_index);
    k_scan<<<1, 1024, 0, st3>>>();
    k_fill<<<Ee / 1024, 256, 0, st3>>>(edge_index);
    if (use2) cudaEventRecord(evC, st3);

    // ---- stream 0: GIN chain ----
    k_proj78<<<Nn / 64, 256>>>(x, w1a);
    if (use2) cudaStreamWaitEvent(0, evC, 0);
    k_mlp<<<Nn / 64, 512>>>(0, b1a, w1b, b1b);
    for (int l = 0; l < 4; l++) {
        k_proj32<<<Nn / 64, 256>>>(l, gamma + l * 32, beta + l * 32, wa + l * 1024);
        k_mlp<<<Nn / 64, 512>>>(l + 1, ba + l * 32, wb + l * 1024, bb + l * 32);
    }
    k_pool<<<Nn / 256, 256>>>(batch, gamma + 128, beta + 128);
    gemm_xd<<<16, 256>>>(hgP, w_fcxd, b_fcxd, xcP);

    if (use2) {
        cudaEventRecord(evJ, st2);
        cudaStreamWaitEvent(0, evJ, 0);
    }

    // ---- joint head ----
    gemm128<64, 4, false, true><<<dim3(8, 16, 1), 256>>>(
        xcP, w_fc1, b_fc1, f1P, 256, 1024, 256, nullptr);
    gemm128<64, 4, true, false><<<dim3(8, 4, 4), 256>>>(
        f1P, w_fc2, nullptr, nullptr, 1024, 0, 256, partP);
    k_out<<<Bb, 256>>>(b_fc2, w_out, b_out, out);
}

// round 11
// speedup vs baseline: 1.0089x; 1.0089x over previous
#include <cuda_runtime.h>

#define Nn 65536
#define Ee 2097152
#define Bb 1024
#define FXDIM 78
#define DIM 32
#define EMBD 128
#define VOCAB 26
#define PLENN 1000
#define KSZ 8
#define CLENN 121
#define NFIL 32
#define ADIM 6656   /* VOCAB * NFIL * KSZ */
#define A4 1664     /* ADIM/4 */
#define OUTDIM 128
#define SSTR 64          /* stats stride in floats (256B) to spread atomics */
#define SSLOT (2 * 64 * SSTR)   /* floats per layer slot: sum[64*64] + sq[64*64] */

// ---------------- scratch (device globals; no allocations) ----------------
__device__ __align__(16) float g_p[Nn * DIM];
__device__ __align__(16) float g_y[Nn * DIM];
__device__ float g_stats[5 * SSLOT];   // spread: sum @ slot*SSLOT + c*SSTR, sq @ +64*SSTR
__device__ float g_hg[Bb * DIM];
__device__ __align__(16) float g_xc[Bb * 256];    // [xd | xt]
__device__ __align__(16) float g_f1[Bb * 1024];
__device__ __align__(16) float g_Wt[PLENN * 256]; // conv_w transposed to [p][f*8+k]
__device__ __align__(16) float g_A[Bb * ADIM];
__device__ __align__(16) float g_U[ADIM * OUTDIM];
__device__ __align__(16) float g_bias2[OUTDIM];
__device__ __align__(16) float g_part[16 * 1024 * 128];   // split-K partials (8 MB)
// CSR scratch
__device__ __align__(16) int g_off[Nn + 4];
__device__ __align__(16) int g_pos[Nn];
__device__ __align__(16) int g_srcl[Ee];

__device__ __forceinline__ void f4add(float4& a, const float4& b) {
    a.x += b.x; a.y += b.y; a.z += b.z; a.w += b.w;
}

// ---------------- init ----------------
__global__ void k_init() {
    int i = blockIdx.x * 256 + threadIdx.x;   // 65536 threads
    if (i < Nn) g_pos[i] = 0;
    if (i < Bb * DIM) g_hg[i] = 0.f;
    if (i < 5 * SSLOT) g_stats[i] = 0.f;
    if (i < OUTDIM) g_bias2[i] = 0.f;
}

// ---------------- CSR build (vectorized) ----------------
__global__ void k_hist(const int* __restrict__ ei) {
    int e4 = blockIdx.x * 256 + threadIdx.x;
    int4 d = ((const int4*)(ei + Ee))[e4];
    atomicAdd(&g_pos[d.x], 1);
    atomicAdd(&g_pos[d.y], 1);
    atomicAdd(&g_pos[d.z], 1);
    atomicAdd(&g_pos[d.w], 1);
}

__global__ void k_scan() {  // 1 block, 1024 threads, 64 elems each
    int t = threadIdx.x, lane = t & 31, wid = t >> 5;
    __shared__ int ws[32];
    const int4* pos4 = (const int4*)g_pos;
    int base4 = t * 16;
    int s = 0;
#pragma unroll
    for (int j = 0; j < 16; j++) {
        int4 v = pos4[base4 + j];
        s += v.x + v.y + v.z + v.w;
    }
    int v = s;
#pragma unroll
    for (int off = 1; off < 32; off <<= 1) {
        int u = __shfl_up_sync(0xffffffffu, v, off);
        if (lane >= off) v += u;
    }
    if (lane == 31) ws[wid] = v;
    __syncthreads();
    if (wid == 0) {
        int w = ws[lane];
#pragma unroll
        for (int off = 1; off < 32; off <<= 1) {
            int u = __shfl_up_sync(0xffffffffu, w, off);
            if (lane >= off) w += u;
        }
        ws[lane] = w;
    }
    __syncthreads();
    int run = v - s + (wid ? ws[wid - 1] : 0);
    int4* off4 = (int4*)g_off;
    int4* posw4 = (int4*)g_pos;
#pragma unroll
    for (int j = 0; j < 16; j++) {
        int4 d = pos4[base4 + j];
        int4 o;
        o.x = run;
        o.y = run + d.x;
        o.z = o.y + d.y;
        o.w = o.z + d.z;
        off4[base4 + j] = o;
        posw4[base4 + j] = o;
        run = o.w + d.w;
    }
    if (t == 1023) g_off[Nn] = run;
}

__global__ void k_fill(const int* __restrict__ ei) {
    int e4 = blockIdx.x * 256 + threadIdx.x;
    int4 sv = ((const int4*)ei)[e4];
    int4 dv = ((const int4*)(ei + Ee))[e4];
    int s0 = atomicAdd(&g_pos[dv.x], 1); g_srcl[s0] = sv.x;
    int s1 = atomicAdd(&g_pos[dv.y], 1); g_srcl[s1] = sv.y;
    int s2 = atomicAdd(&g_pos[dv.z], 1); g_srcl[s2] = sv.z;
    int s3 = atomicAdd(&g_pos[dv.w], 1); g_srcl[s3] = sv.w;
}

// ---------------- protein branch ----------------
__global__ void k_transpose(const float* __restrict__ conv_w) {
    int f = blockIdx.x;
    for (int i = threadIdx.x; i < PLENN * KSZ; i += 256) {
        int p = i >> 3, k = i & 7;
        g_Wt[p * 256 + f * 8 + k] = conv_w[f * PLENN * KSZ + i];
    }
}

// 4 proteins per block; 64 threads per protein, float4 smem RMW
__global__ void k_buildA4(const int* __restrict__ target) {
    extern __shared__ float4 sA4[];
    int tid = threadIdx.x;
    int b0 = blockIdx.x * 4;
    int pg = tid >> 6;          // protein slot 0..3
    int col4 = tid & 63;        // float4 column
    for (int i = tid; i < 4 * A4; i += 256) sA4[i] = make_float4(0.f, 0.f, 0.f, 0.f);
    __syncthreads();
    const float4* Wt4 = (const float4*)g_Wt;
    const int* tp = target + (b0 + pg) * PLENN;
    int pbase = pg * A4;
    for (int p = 0; p < PLENN; p += 2) {
        int va = tp[p], vb = tp[p + 1];
        float4 w0 = Wt4[p * 64 + col4];
        float4 w1 = Wt4[(p + 1) * 64 + col4];
        int ia = pbase + va * 64 + col4;
        float4 Aa = sA4[ia]; f4add(Aa, w0); sA4[ia] = Aa;
        int ib = pbase + vb * 64 + col4;
        float4 Ab = sA4[ib]; f4add(Ab, w1); sA4[ib] = Ab;
    }
    __syncthreads();
    float4* gA4 = (float4*)g_A;
    for (int j = 0; j < 4; j++)
        for (int i = tid; i < A4; i += 256)
            gA4[(b0 + j) * A4 + i] = sA4[j * A4 + i];
}

// U[(v*256+f*8+k)*128+o] = sum_t emb[v*128+t+k] * w_fcxt[(f*121+t)*128+o]
__global__ void k_buildU(const float* __restrict__ emb, const float* __restrict__ wfcxt) {
    __shared__ float se[EMBD];
    int f = blockIdx.x, v = blockIdx.y, o = threadIdx.x;
    se[o] = emb[v * EMBD + o];
    __syncthreads();
    float acc[KSZ];
#pragma unroll
    for (int k = 0; k < KSZ; k++) acc[k] = 0.f;
    const float* wf = wfcxt + f * CLENN * OUTDIM + o;
#pragma unroll 4
    for (int t = 0; t < CLENN; t++) {
        float wv = wf[t * OUTDIM];
#pragma unroll
        for (int k = 0; k < KSZ; k++) acc[k] += se[t + k] * wv;
    }
#pragma unroll
    for (int k = 0; k < KSZ; k++)
        g_U[(v * 256 + f * 8 + k) * OUTDIM + o] = acc[k];
}

__global__ void k_bias2(const float* __restrict__ wfcxt, const float* __restrict__ conv_b) {
    int f = blockIdx.x, o = threadIdx.x; // 128 threads
    float s = 0.f;
    for (int t = 0; t < CLENN; t++) s += wfcxt[(f * CLENN + t) * OUTDIM + o];
    atomicAdd(&g_bias2[o], s * conv_b[f]);
}

// ---------------- GIN layers ----------------
__global__ void k_proj78(const float* __restrict__ x, const float* __restrict__ W) {
    __shared__ float xs[64][80];
    __shared__ float ws[78][33];
    int tid = threadIdx.x;
    int row0 = blockIdx.x * 64;
    const float* xb = x + row0 * FXDIM;
    for (int i = tid; i < 64 * FXDIM; i += 256) xs[i / FXDIM][i % FXDIM] = xb[i];
    for (int i = tid; i < FXDIM * 32; i += 256) ws[i >> 5][i & 31] = W[i];
    __syncthreads();
    int c = tid & 31, w = tid >> 5;
    float acc[8];
#pragma unroll
    for (int j = 0; j < 8; j++) acc[j] = 0.f;
    for (int k = 0; k < FXDIM; k++) {
        float wv = ws[k][c];
#pragma unroll
        for (int j = 0; j < 8; j++) acc[j] += xs[w * 8 + j][k] * wv;
    }
#pragma unroll
    for (int j = 0; j < 8; j++) g_p[(row0 + w * 8 + j) * 32 + c] = acc[j];
}

// p = (y * s + t) @ W ; BN fold computed inline from spread stats slot
__global__ void k_proj32(int slot, const float* __restrict__ gamma,
                         const float* __restrict__ beta, const float* __restrict__ W) {
    __shared__ float xs[64][33];
    __shared__ float ws[32][33];
    __shared__ float sa[64];
    int tid = threadIdx.x;
    int row0 = blockIdx.x * 64;
    if (tid < 32) {
        float m = g_stats[slot * SSLOT + tid * SSTR] * (1.f / Nn);
        float v = g_stats[slot * SSLOT + 64 * SSTR + tid * SSTR] * (1.f / Nn) - m * m;
        float s = gamma[tid] * rsqrtf(v + 1e-5f);
        sa[tid] = s;
        sa[32 + tid] = beta[tid] - m * s;
    }
    __syncthreads();
    const float4* y4 = (const float4*)g_y;
    for (int i = tid; i < 512; i += 256) {
        int r = i >> 3, q = i & 7;
        float4 v = y4[(row0 + r) * 8 + q];
        xs[r][q * 4 + 0] = v.x * sa[q * 4 + 0] + sa[32 + q * 4 + 0];
        xs[r][q * 4 + 1] = v.y * sa[q * 4 + 1] + sa[32 + q * 4 + 1];
        xs[r][q * 4 + 2] = v.z * sa[q * 4 + 2] + sa[32 + q * 4 + 2];
        xs[r][q * 4 + 3] = v.w * sa[q * 4 + 3] + sa[32 + q * 4 + 3];
    }
    for (int i = tid; i < 1024; i += 256) ws[i >> 5][i & 31] = W[i];
    __syncthreads();
    int c = tid & 31, w = tid >> 5;
    float acc[8];
#pragma unroll
    for (int j = 0; j < 8; j++) acc[j] = 0.f;
#pragma unroll
    for (int k = 0; k < 32; k++) {
        float wv = ws[k][c];
#pragma unroll
        for (int j = 0; j < 8; j++) acc[j] += xs[w * 8 + j][k] * wv;
    }
#pragma unroll
    for (int j = 0; j < 8; j++) g_p[(row0 + w * 8 + j) * 32 + c] = acc[j];
}

// fused: CSR gather (16 edges in flight via 4 accumulators) + MLP + ReLU + spread BN stats
__global__ void k_mlp(int layer, const float* __restrict__ ba, const float* __restrict__ Wb,
                      const float* __restrict__ bb) {
    __shared__ float us[64][33];
    __shared__ float ws[32][33];
    __shared__ float r1[8][32];
    __shared__ float r2[8][32];
    __shared__ float bsh[32], bbsh[32];
    int tid = threadIdx.x;
    int lane = tid & 31, wid = tid >> 5;
    int row0 = blockIdx.x * 64;
    if (tid < 32) { bsh[tid] = ba[tid]; bbsh[tid] = bb[tid]; }
    for (int i = tid; i < 1024; i += 256) ws[i >> 5][i & 31] = Wb[i];
    __syncthreads();
    const float4* p4 = (const float4*)g_p;
    int eg = lane >> 3;   // edge slot 0..3
    int q = lane & 7;     // float4 chunk
    for (int nn = wid; nn < 64; nn += 8) {
        int node = row0 + nn;
        float4 a0 = make_float4(0.f, 0.f, 0.f, 0.f);
        float4 a1 = a0, a2 = a0, a3 = a0;
        if (eg == 0) a0 = p4[node * 8 + q];  // self term
        int i = g_off[node], ib = g_off[node + 1];
        for (; i + 16 <= ib; i += 16) {
            int s0 = g_srcl[i + eg];
            int s1 = g_srcl[i + 4 + eg];
            int s2 = g_srcl[i + 8 + eg];
            int s3 = g_srcl[i + 12 + eg];
            float4 v0 = p4[s0 * 8 + q];
            float4 v1 = p4[s1 * 8 + q];
            float4 v2 = p4[s2 * 8 + q];
            float4 v3 = p4[s3 * 8 + q];
            f4add(a0, v0);
            f4add(a1, v1);
            f4add(a2, v2);
            f4add(a3, v3);
        }
        for (; i + 4 <= ib; i += 4) f4add(a1, p4[g_srcl[i + eg] * 8 + q]);
        if (eg < ib - i) f4add(a2, p4[g_srcl[i + eg] * 8 + q]);
        f4add(a0, a1);
        f4add(a2, a3);
        f4add(a0, a2);
#pragma unroll
        for (int off = 8; off <= 16; off <<= 1) {
            a0.x += __shfl_xor_sync(0xffffffffu, a0.x, off);
            a0.y += __shfl_xor_sync(0xffffffffu, a0.y, off);
            a0.z += __shfl_xor_sync(0xffffffffu, a0.z, off);
            a0.w += __shfl_xor_sync(0xffffffffu, a0.w, off);
        }
        if (eg == 0) {
            us[nn][q * 4 + 0] = fmaxf(a0.x + bsh[q * 4 + 0], 0.f);
            us[nn][q * 4 + 1] = fmaxf(a0.y + bsh[q * 4 + 1], 0.f);
            us[nn][q * 4 + 2] = fmaxf(a0.z + bsh[q * 4 + 2], 0.f);
            us[nn][q * 4 + 3] = fmaxf(a0.w + bsh[q * 4 + 3], 0.f);
        }
    }
    __syncthreads();
    int c = lane, w = wid;
    float acc[8];
#pragma unroll
    for (int j = 0; j < 8; j++) acc[j] = bbsh[c];
#pragma unroll
    for (int k = 0; k < 32; k++) {
        float wv = ws[k][c];
#pragma unroll
        for (int j = 0; j < 8; j++) acc[j] += us[w * 8 + j][k] * wv;
    }
    float s1 = 0.f, s2 = 0.f;
#pragma unroll
    for (int j = 0; j < 8; j++) {
        float v = fmaxf(acc[j], 0.f);
        g_y[(row0 + w * 8 + j) * 32 + c] = v;
        s1 += v;
        s2 += v * v;
    }
    r1[w][c] = s1;
    r2[w][c] = s2;
    __syncthreads();
    if (w == 0) {
        float a = 0.f, b2 = 0.f;
#pragma unroll
        for (int qq = 0; qq < 8; qq++) { a += r1[qq][c]; b2 += r2[qq][c]; }
        // spread atomics: 256B stride per channel -> distinct L2 lines/slices
        atomicAdd(&g_stats[layer * SSLOT + c * SSTR], a);
        atomicAdd(&g_stats[layer * SSLOT + 64 * SSTR + c * SSTR], b2);
    }
}

// global add pool: run-length accumulation + float4 reads, BN fold inline (slot 4)
__global__ void k_pool(const int* __restrict__ batch, const float* __restrict__ gamma,
                       const float* __restrict__ beta) {
    int tid = threadIdx.x;
    int lane = tid & 31;
    int gwarp = blockIdx.x * 8 + (tid >> 5);
    int q = lane & 7, sub = lane >> 3;
    int base = gwarp * 32;
    float s[4], t[4];
#pragma unroll
    for (int c = 0; c < 4; c++) {
        int d = q * 4 + c;
        float m = g_stats[4 * SSLOT + d * SSTR] * (1.f / Nn);
        float vv = g_stats[4 * SSLOT + 64 * SSTR + d * SSTR] * (1.f / Nn) - m * m;
        s[c] = gamma[d] * rsqrtf(vv + 1e-5f);
        t[c] = beta[d] - m * s[c];
    }
    const float4* y4 = (const float4*)g_y;
    float4 acc = make_float4(0.f, 0.f, 0.f, 0.f);
    int cur = batch[base + sub];
#pragma unroll 2
    for (int j = 0; j < 8; j++) {
        int node = base + j * 4 + sub;
        int b = batch[node];
        float4 v = y4[node * 8 + q];
        v.x = v.x * s[0] + t[0];
        v.y = v.y * s[1] + t[1];
        v.z = v.z * s[2] + t[2];
        v.w = v.w * s[3] + t[3];
        if (b != cur) {
            atomicAdd(&g_hg[cur * 32 + q * 4 + 0], acc.x);
            atomicAdd(&g_hg[cur * 32 + q * 4 + 1], acc.y);
            atomicAdd(&g_hg[cur * 32 + q * 4 + 2], acc.z);
            atomicAdd(&g_hg[cur * 32 + q * 4 + 3], acc.w);
            acc = make_float4(0.f, 0.f, 0.f, 0.f);
            cur = b;
        }
        f4add(acc, v);
    }
    atomicAdd(&g_hg[cur * 32 + q * 4 + 0], acc.x);
    atomicAdd(&g_hg[cur * 32 + q * 4 + 1], acc.y);
    atomicAdd(&g_hg[cur * 32 + q * 4 + 2], acc.z);
    atomicAdd(&g_hg[cur * 32 + q * 4 + 3], acc.w);
}

// ---------------- high-efficiency SGEMM: BM=128, BK=16, 256 threads ----------------
template <int BN, int TN, bool PARTIAL, bool RELU>
__global__ void gemm128(const float* __restrict__ A, const float* __restrict__ W,
                        const float* __restrict__ bias, float* __restrict__ C,
                        int K, int ldc, int kChunk, float* __restrict__ part) {
    const int N = gridDim.y * BN;
    __shared__ float As[16][132];
    __shared__ float Ws[16][BN];
    int tid = threadIdx.x;
    int tx = tid & 15, ty = tid >> 4;
    int row0 = blockIdx.x * 128;
    int col0 = blockIdx.y * BN;
    int k0 = blockIdx.z * kChunk;
    int k1 = k0 + kChunk;
    if (k1 > K) k1 = K;
    float acc[8][TN];
#pragma unroll
    for (int i = 0; i < 8; i++)
#pragma unroll
        for (int j = 0; j < TN; j++) acc[i][j] = 0.f;

    int ar = tid >> 2;
    int ak = (tid & 3) * 4;
    int wr = tid >> 4;
    int wc = (tid & 15) * (BN / 16);

    for (int kb = k0; kb < k1; kb += 16) {
        const float* Ap = A + (row0 + ar) * K + kb + ak;
        float4 va = *(const float4*)Ap;
        float4 vb = *(const float4*)(Ap + 64 * K);
        As[ak + 0][ar] = va.x; As[ak + 1][ar] = va.y;
        As[ak + 2][ar] = va.z; As[ak + 3][ar] = va.w;
        As[ak + 0][ar + 64] = vb.x; As[ak + 1][ar + 64] = vb.y;
        As[ak + 2][ar + 64] = vb.z; As[ak + 3][ar + 64] = vb.w;
        const float* Wp = W + (kb + wr) * N + col0 + wc;
        if (BN == 128) {
            *(float4*)&Ws[wr][wc] = *(const float4*)Wp;
            *(float4*)&Ws[wr][wc + 4] = *(const float4*)(Wp + 4);
        } else {
            *(float4*)&Ws[wr][wc] = *(const float4*)Wp;
        }
        __syncthreads();
#pragma unroll
        for (int kk = 0; kk < 16; kk++) {
            float av[8], bv[TN];
            *(float4*)&av[0] = *(const float4*)&As[kk][ty * 8];
            *(float4*)&av[4] = *(const float4*)&As[kk][ty * 8 + 4];
            *(float4*)&bv[0] = *(const float4*)&Ws[kk][tx * 4];
            if (TN == 8) *(float4*)&bv[4] = *(const float4*)&Ws[kk][64 + tx * 4];
#pragma unroll
            for (int i = 0; i < 8; i++)
#pragma unroll
                for (int j = 0; j < TN; j++) acc[i][j] += av[i] * bv[j];
        }
        __syncthreads();
    }

    if (PARTIAL) {
        const int Mtot = gridDim.x * 128;
        float* P = part + (size_t)blockIdx.z * Mtot * N;
#pragma unroll
        for (int i = 0; i < 8; i++) {
            int r = row0 + ty * 8 + i;
            *(float4*)&P[r * N + col0 + tx * 4] = *(float4*)&acc[i][0];
            if (TN == 8)
                *(float4*)&P[r * N + col0 + 64 + tx * 4] = *(float4*)&acc[i][4];
        }
    } else {
#pragma unroll
        for (int i = 0; i < 8; i++) {
            int r = row0 + ty * 8 + i;
#pragma unroll
            for (int h = 0; h < TN / 4; h++) {
                int c = col0 + h * 64 + tx * 4;
                float4 v;
                v.x = acc[i][h * 4 + 0] + (bias ? bias[c + 0] : 0.f);
                v.y = acc[i][h * 4 + 1] + (bias ? bias[c + 1] : 0.f);
                v.z = acc[i][h * 4 + 2] + (bias ? bias[c + 2] : 0.f);
                v.w = acc[i][h * 4 + 3] + (bias ? bias[c + 3] : 0.f);
                if (RELU) {
                    v.x = fmaxf(v.x, 0.f); v.y = fmaxf(v.y, 0.f);
                    v.z = fmaxf(v.z, 0.f); v.w = fmaxf(v.w, 0.f);
                }
                *(float4*)&C[r * ldc + c] = v;
            }
        }
    }
}

// reduce xt partials (16 splits, 1024x128) into g_xc[:,128:256] with both biases
__global__ void k_reduce_xt(const float* __restrict__ b_fcxt) {
    int idx4 = blockIdx.x * 256 + threadIdx.x;   // 32768 float4s
    int i = idx4 * 4;
    int b = i >> 7, col = i & 127;
    const float4* P = (const float4*)g_part;
    float4 s = P[idx4];
#pragma unroll
    for (int k = 1; k < 16; k++) f4add(s, P[k * (Bb * 128 / 4) + idx4]);
    float4 bs = *(const float4*)&g_bias2[col];
    float4 bf = *(const float4*)&b_fcxt[col];
    s.x += bs.x + bf.x; s.y += bs.y + bf.y;
    s.z += bs.z + bf.z; s.w += bs.w + bf.w;
    *(float4*)&g_xc[b * 256 + 128 + col] = s;
}

// ---------------- small GEMM for xd (M=1024,K=32,N=128) ----------------
__global__ void gemm_xd(const float* __restrict__ A, const float* __restrict__ W,
                        const float* __restrict__ bias, float* __restrict__ C) {
    __shared__ float As[64][33];
    __shared__ float Ws[32][128];
    int tid = threadIdx.x;
    int row0 = blockIdx.x * 64;
    for (int i = tid; i < 64 * 32; i += 256) As[i >> 5][i & 31] = A[row0 * 32 + i];
    for (int i = tid; i < 32 * 128; i += 256) Ws[i >> 7][i & 127] = W[i];
    __syncthreads();
    int tx = tid & 31, ty = tid >> 5;
    float acc[8][4];
#pragma unroll
    for (int i = 0; i < 8; i++)
#pragma unroll
        for (int m = 0; m < 4; m++) acc[i][m] = 0.f;
#pragma unroll
    for (int k = 0; k < 32; k++) {
        float rw[4];
#pragma unroll
        for (int m = 0; m < 4; m++) rw[m] = Ws[k][tx + 32 * m];
#pragma unroll
        for (int i = 0; i < 8; i++) {
            float ra = As[ty * 8 + i][k];
#pragma unroll
            for (int m = 0; m < 4; m++) acc[i][m] += ra * rw[m];
        }
    }
#pragma unroll
    for (int i = 0; i < 8; i++) {
        int r = row0 + ty * 8 + i;
#pragma unroll
        for (int m = 0; m < 4; m++) {
            int c = tx + 32 * m;
            C[r * 256 + c] = fmaxf(acc[i][m] + bias[c], 0.f);
        }
    }
}

// ---------------- final head: reduce fc2 partials + bias + relu + dot w_out ----------------
__global__ void k_out(const float* __restrict__ b_fc2, const float* __restrict__ wout,
                      const float* __restrict__ bout, float* __restrict__ out) {
    int b = blockIdx.x, c = threadIdx.x; // 256 threads
    float s = g_part[b * 256 + c];
#pragma unroll
    for (int k = 1; k < 4; k++) s += g_part[k * (Bb * 256) + b * 256 + c];
    float v = fmaxf(s + b_fc2[c], 0.f) * wout[c];
#pragma unroll
    for (int off = 16; off; off >>= 1) v += __shfl_down_sync(0xffffffffu, v, off);
    __shared__ float ps[8];
    if ((c & 31) == 0) ps[c >> 5] = v;
    __syncthreads();
    if (c == 0) {
        float t = bout[0];
#pragma unroll
        for (int q = 0; q < 8; q++) t += ps[q];
        out[b] = t;
    }
}

// ---------------- launcher ----------------
extern "C" void kernel_launch(void* const* d_in, const int* in_sizes, int n_in,
                              void* d_out, int out_size) {
    const float* x = (const float*)d_in[0];
    const int* edge_index = (const int*)d_in[1];
    const int* batch = (const int*)d_in[2];
    const int* target = (const int*)d_in[3];
    const float* w1a = (const float*)d_in[4];
    const float* b1a = (const float*)d_in[5];
    const float* w1b = (const float*)d_in[6];
    const float* b1b = (const float*)d_in[7];
    const float* wa = (const float*)d_in[8];
    const float* ba = (const float*)d_in[9];
    const float* wb = (const float*)d_in[10];
    const float* bb = (const float*)d_in[11];
    const float* gamma = (const float*)d_in[12];
    const float* beta = (const float*)d_in[13];
    const float* w_fcxd = (const float*)d_in[14];
    const float* b_fcxd = (const float*)d_in[15];
    const float* emb = (const float*)d_in[16];
    const float* conv_w = (const float*)d_in[17];
    const float* conv_b = (const float*)d_in[18];
    const float* w_fcxt = (const float*)d_in[19];
    const float* b_fcxt = (const float*)d_in[20];
    const float* w_fc1 = (const float*)d_in[21];
    const float* b_fc1 = (const float*)d_in[22];
    const float* w_fc2 = (const float*)d_in[23];
    const float* b_fc2 = (const float*)d_in[24];
    const float* w_out = (const float*)d_in[25];
    const float* b_out = (const float*)d_in[26];
    float* out = (float*)d_out;

    float *hgP, *xcP, *f1P, *AP, *UP, *partP;
    cudaGetSymbolAddress((void**)&hgP, g_hg);
    cudaGetSymbolAddress((void**)&xcP, g_xc);
    cudaGetSymbolAddress((void**)&f1P, g_f1);
    cudaGetSymbolAddress((void**)&AP, g_A);
    cudaGetSymbolAddress((void**)&UP, g_U);
    cudaGetSymbolAddress((void**)&partP, g_part);

    cudaFuncSetAttribute(k_buildA4, cudaFuncAttributeMaxDynamicSharedMemorySize,
                         4 * ADIM * (int)sizeof(float));

    // one-time streams (fork-join capture pattern)
    static cudaStream_t s2 = 0, s3 = 0;
    static cudaEvent_t evF = 0, evJ = 0, evC = 0;
    static bool tried = false;
    static bool use2 = false;
    if (!tried) {
        tried = true;
        if (cudaStreamCreateWithFlags(&s2, cudaStreamNonBlocking) == cudaSuccess &&
            cudaStreamCreateWithFlags(&s3, cudaStreamNonBlocking) == cudaSuccess &&
            cudaEventCreateWithFlags(&evF, cudaEventDisableTiming) == cudaSuccess &&
            cudaEventCreateWithFlags(&evJ, cudaEventDisableTiming) == cudaSuccess &&
            cudaEventCreateWithFlags(&evC, cudaEventDisableTiming) == cudaSuccess) {
            use2 = true;
        }
    }
    cudaStream_t st2 = use2 ? s2 : (cudaStream_t)0;
    cudaStream_t st3 = use2 ? s3 : (cudaStream_t)0;

    // launch #1
    k_init<<<256, 256>>>();

    if (use2) {
        cudaEventRecord(evF, 0);
        cudaStreamWaitEvent(st2, evF, 0);
        cudaStreamWaitEvent(st3, evF, 0);
    }

    // ---- stream 3: CSR build (launches #2-#4; overlaps proj78) ----
    k_hist<<<Ee / 1024, 256, 0, st3>>>(edge_index);
    k_scan<<<1, 1024, 0, st3>>>();
    k_fill<<<Ee / 1024, 256, 0, st3>>>(edge_index);
    if (use2) cudaEventRecord(evC, st3);

    // ---- stream 0: GIN chain (launch #5 = proj78, #6 = k_mlp -> ncu capture) ----
    k_proj78<<<Nn / 64, 256>>>(x, w1a);
    if (use2) cudaStreamWaitEvent(0, evC, 0);
    k_mlp<<<Nn / 64, 256>>>(0, b1a, w1b, b1b);
    for (int l = 0; l < 4; l++) {
        k_proj32<<<Nn / 64, 256>>>(l, gamma + l * 32, beta + l * 32, wa + l * 1024);
        k_mlp<<<Nn / 64, 256>>>(l + 1, ba + l * 32, wb + l * 1024, bb + l * 32);
    }
    k_pool<<<Nn / 256, 256>>>(batch, gamma + 128, beta + 128);
    gemm_xd<<<16, 256>>>(hgP, w_fcxd, b_fcxd, xcP);

    // ---- stream 2: protein branch + xt GEMM (enqueued late; runs concurrently via events) ----
    k_transpose<<<NFIL, 256, 0, st2>>>(conv_w);
    k_buildA4<<<Bb / 4, 256, 4 * ADIM * sizeof(float), st2>>>(target);
    k_buildU<<<dim3(NFIL, VOCAB), 128, 0, st2>>>(emb, w_fcxt);
    k_bias2<<<NFIL, 128, 0, st2>>>(w_fcxt, conv_b);
    gemm128<128, 8, true, false><<<dim3(8, 1, 16), 256, 0, st2>>>(
        AP, UP, nullptr, nullptr, ADIM, 0, 416, partP);
    k_reduce_xt<<<128, 256, 0, st2>>>(b_fcxt);

    if (use2) {
        cudaEventRecord(evJ, st2);
        cudaStreamWaitEvent(0, evJ, 0);
    }

    // ---- joint head ----
    gemm128<64, 4, false, true><<<dim3(8, 16, 1), 256>>>(
        xcP, w_fc1, b_fc1, f1P, 256, 1024, 256, nullptr);
    gemm128<64, 4, true, false><<<dim3(8, 4, 4), 256>>>(
        f1P, w_fc2, nullptr, nullptr, 1024, 0, 256, partP);
    k_out<<<Bb, 256>>>(b_fc2, w_out, b_out, out);
}

// round 12
// speedup vs baseline: 1.0317x; 1.0225x over previous
#include <cuda_runtime.h>

#define Nn 65536
#define Ee 2097152
#define Bb 1024
#define FXDIM 78
#define DIM 32
#define EMBD 128
#define VOCAB 26
#define PLENN 1000
#define KSZ 8
#define CLENN 121
#define NFIL 32
#define ADIM 6656   /* VOCAB * NFIL * KSZ */
#define A4 1664     /* ADIM/4 */
#define OUTDIM 128
#define SSTR 64          /* stats stride in floats (256B) to spread atomics */
#define SSLOT (2 * 64 * SSTR)   /* floats per layer slot */

// ---------------- scratch (device globals; no allocations) ----------------
__device__ __align__(16) float g_p[Nn * DIM];
__device__ __align__(16) float g_y[Nn * DIM];
__device__ float g_stats[5 * SSLOT];
__device__ float g_hg[Bb * DIM];
__device__ __align__(16) float g_xc[Bb * 256];    // [xd | xt]
__device__ __align__(16) float g_f1[Bb * 1024];
__device__ __align__(16) float g_Wt[PLENN * 256]; // conv_w transposed to [p][f*8+k]
__device__ __align__(16) float g_A[Bb * ADIM];
__device__ __align__(16) float g_U[ADIM * OUTDIM];
__device__ __align__(16) float g_bias2[OUTDIM];
__device__ __align__(16) float g_part[16 * 1024 * 128];   // split-K partials (8 MB)
// CSR scratch (8-way privatized histogram to kill same-address atomic serialization)
__device__ __align__(16) int g_hist8[8 * Nn];
__device__ __align__(16) int g_base8[8 * Nn];
__device__ __align__(16) int g_off[Nn + 4];
__device__ __align__(16) int g_pos[Nn];
__device__ __align__(16) int g_srcl[Ee];

__device__ __forceinline__ void f4add(float4& a, const float4& b) {
    a.x += b.x; a.y += b.y; a.z += b.z; a.w += b.w;
}

// ---------------- init ----------------
__global__ void k_init() {
    int i = blockIdx.x * 256 + threadIdx.x;   // 65536 threads
    int4* h4 = (int4*)g_hist8;                // 131072 int4s
    h4[i * 2 + 0] = make_int4(0, 0, 0, 0);
    h4[i * 2 + 1] = make_int4(0, 0, 0, 0);
    if (i < Bb * DIM) g_hg[i] = 0.f;
    if (i < 5 * SSLOT) g_stats[i] = 0.f;
    if (i < OUTDIM) g_bias2[i] = 0.f;
}

// ---------------- CSR build (8-way privatized) ----------------
__global__ void k_hist(const int* __restrict__ ei) {
    int e4 = blockIdx.x * 256 + threadIdx.x;
    int* H = g_hist8 + (blockIdx.x & 7) * Nn;
    int4 d = ((const int4*)(ei + Ee))[e4];
    atomicAdd(&H[d.x], 1);
    atomicAdd(&H[d.y], 1);
    atomicAdd(&H[d.z], 1);
    atomicAdd(&H[d.w], 1);
}

// per-node totals across the 8 copies
__global__ void k_tot() {
    int n = blockIdx.x * 1024 + threadIdx.x;   // grid 64
    int s = 0;
#pragma unroll
    for (int c = 0; c < 8; c++) s += g_hist8[c * Nn + n];
    g_pos[n] = s;
}

__global__ void k_scan() {  // 1 block, 1024 threads, 64 elems each
    int t = threadIdx.x, lane = t & 31, wid = t >> 5;
    __shared__ int ws[32];
    const int4* pos4 = (const int4*)g_pos;
    int base4 = t * 16;
    int s = 0;
#pragma unroll
    for (int j = 0; j < 16; j++) {
        int4 v = pos4[base4 + j];
        s += v.x + v.y + v.z + v.w;
    }
    int v = s;
#pragma unroll
    for (int off = 1; off < 32; off <<= 1) {
        int u = __shfl_up_sync(0xffffffffu, v, off);
        if (lane >= off) v += u;
    }
    if (lane == 31) ws[wid] = v;
    __syncthreads();
    if (wid == 0) {
        int w = ws[lane];
#pragma unroll
        for (int off = 1; off < 32; off <<= 1) {
            int u = __shfl_up_sync(0xffffffffu, w, off);
            if (lane >= off) w += u;
        }
        ws[lane] = w;
    }
    __syncthreads();
    int run = v - s + (wid ? ws[wid - 1] : 0);
    int4* off4 = (int4*)g_off;
#pragma unroll
    for (int j = 0; j < 16; j++) {
        int4 d = pos4[base4 + j];
        int4 o;
        o.x = run;
        o.y = run + d.x;
        o.z = o.y + d.y;
        o.w = o.z + d.z;
        off4[base4 + j] = o;
        run = o.w + d.w;
    }
    if (t == 1023) g_off[Nn] = run;
}

// per-(copy,node) base offsets
__global__ void k_base() {
    int n = blockIdx.x * 1024 + threadIdx.x;   // grid 64
    int run = g_off[n];
#pragma unroll
    for (int c = 0; c < 8; c++) {
        g_base8[c * Nn + n] = run;
        run += g_hist8[c * Nn + n];
    }
}

__global__ void k_fill(const int* __restrict__ ei) {
    int e4 = blockIdx.x * 256 + threadIdx.x;
    int* B = g_base8 + (blockIdx.x & 7) * Nn;   // same copy mapping as k_hist
    int4 sv = ((const int4*)ei)[e4];
    int4 dv = ((const int4*)(ei + Ee))[e4];
    int s0 = atomicAdd(&B[dv.x], 1); g_srcl[s0] = sv.x;
    int s1 = atomicAdd(&B[dv.y], 1); g_srcl[s1] = sv.y;
    int s2 = atomicAdd(&B[dv.z], 1); g_srcl[s2] = sv.z;
    int s3 = atomicAdd(&B[dv.w], 1); g_srcl[s3] = sv.w;
}

// ---------------- protein branch ----------------
__global__ void k_transpose(const float* __restrict__ conv_w) {
    int f = blockIdx.x;
    for (int i = threadIdx.x; i < PLENN * KSZ; i += 256) {
        int p = i >> 3, k = i & 7;
        g_Wt[p * 256 + f * 8 + k] = conv_w[f * PLENN * KSZ + i];
    }
}

__global__ void k_buildA4(const int* __restrict__ target) {
    extern __shared__ float4 sA4[];
    int tid = threadIdx.x;
    int b0 = blockIdx.x * 4;
    int pg = tid >> 6;
    int col4 = tid & 63;
    for (int i = tid; i < 4 * A4; i += 256) sA4[i] = make_float4(0.f, 0.f, 0.f, 0.f);
    __syncthreads();
    const float4* Wt4 = (const float4*)g_Wt;
    const int* tp = target + (b0 + pg) * PLENN;
    int pbase = pg * A4;
    for (int p = 0; p < PLENN; p += 2) {
        int va = tp[p], vb = tp[p + 1];
        float4 w0 = Wt4[p * 64 + col4];
        float4 w1 = Wt4[(p + 1) * 64 + col4];
        int ia = pbase + va * 64 + col4;
        float4 Aa = sA4[ia]; f4add(Aa, w0); sA4[ia] = Aa;
        int ib = pbase + vb * 64 + col4;
        float4 Ab = sA4[ib]; f4add(Ab, w1); sA4[ib] = Ab;
    }
    __syncthreads();
    float4* gA4 = (float4*)g_A;
    for (int j = 0; j < 4; j++)
        for (int i = tid; i < A4; i += 256)
            gA4[(b0 + j) * A4 + i] = sA4[j * A4 + i];
}

__global__ void k_buildU(const float* __restrict__ emb, const float* __restrict__ wfcxt) {
    __shared__ float se[EMBD];
    int f = blockIdx.x, v = blockIdx.y, o = threadIdx.x;
    se[o] = emb[v * EMBD + o];
    __syncthreads();
    float acc[KSZ];
#pragma unroll
    for (int k = 0; k < KSZ; k++) acc[k] = 0.f;
    const float* wf = wfcxt + f * CLENN * OUTDIM + o;
#pragma unroll 4
    for (int t = 0; t < CLENN; t++) {
        float wv = wf[t * OUTDIM];
#pragma unroll
        for (int k = 0; k < KSZ; k++) acc[k] += se[t + k] * wv;
    }
#pragma unroll
    for (int k = 0; k < KSZ; k++)
        g_U[(v * 256 + f * 8 + k) * OUTDIM + o] = acc[k];
}

__global__ void k_bias2(const float* __restrict__ wfcxt, const float* __restrict__ conv_b) {
    int f = blockIdx.x, o = threadIdx.x; // 128 threads
    float s = 0.f;
    for (int t = 0; t < CLENN; t++) s += wfcxt[(f * CLENN + t) * OUTDIM + o];
    atomicAdd(&g_bias2[o], s * conv_b[f]);
}

// ---------------- GIN layers ----------------
__global__ void k_proj78(const float* __restrict__ x, const float* __restrict__ W) {
    __shared__ float xs[64][80];
    __shared__ float ws[78][33];
    int tid = threadIdx.x;
    int row0 = blockIdx.x * 64;
    const float* xb = x + row0 * FXDIM;
    for (int i = tid; i < 64 * FXDIM; i += 256) xs[i / FXDIM][i % FXDIM] = xb[i];
    for (int i = tid; i < FXDIM * 32; i += 256) ws[i >> 5][i & 31] = W[i];
    __syncthreads();
    int c = tid & 31, w = tid >> 5;
    float acc[8];
#pragma unroll
    for (int j = 0; j < 8; j++) acc[j] = 0.f;
    for (int k = 0; k < FXDIM; k++) {
        float wv = ws[k][c];
#pragma unroll
        for (int j = 0; j < 8; j++) acc[j] += xs[w * 8 + j][k] * wv;
    }
#pragma unroll
    for (int j = 0; j < 8; j++) g_p[(row0 + w * 8 + j) * 32 + c] = acc[j];
}

__global__ void k_proj32(int slot, const float* __restrict__ gamma,
                         const float* __restrict__ beta, const float* __restrict__ W) {
    __shared__ float xs[64][33];
    __shared__ float ws[32][33];
    __shared__ float sa[64];
    int tid = threadIdx.x;
    int row0 = blockIdx.x * 64;
    if (tid < 32) {
        float m = g_stats[slot * SSLOT + tid * SSTR] * (1.f / Nn);
        float v = g_stats[slot * SSLOT + 64 * SSTR + tid * SSTR] * (1.f / Nn) - m * m;
        float s = gamma[tid] * rsqrtf(v + 1e-5f);
        sa[tid] = s;
        sa[32 + tid] = beta[tid] - m * s;
    }
    __syncthreads();
    const float4* y4 = (const float4*)g_y;
    for (int i = tid; i < 512; i += 256) {
        int r = i >> 3, q = i & 7;
        float4 v = y4[(row0 + r) * 8 + q];
        xs[r][q * 4 + 0] = v.x * sa[q * 4 + 0] + sa[32 + q * 4 + 0];
        xs[r][q * 4 + 1] = v.y * sa[q * 4 + 1] + sa[32 + q * 4 + 1];
        xs[r][q * 4 + 2] = v.z * sa[q * 4 + 2] + sa[32 + q * 4 + 2];
        xs[r][q * 4 + 3] = v.w * sa[q * 4 + 3] + sa[32 + q * 4 + 3];
    }
    for (int i = tid; i < 1024; i += 256) ws[i >> 5][i & 31] = W[i];
    __syncthreads();
    int c = tid & 31, w = tid >> 5;
    float acc[8];
#pragma unroll
    for (int j = 0; j < 8; j++) acc[j] = 0.f;
#pragma unroll
    for (int k = 0; k < 32; k++) {
        float wv = ws[k][c];
#pragma unroll
        for (int j = 0; j < 8; j++) acc[j] += xs[w * 8 + j][k] * wv;
    }
#pragma unroll
    for (int j = 0; j < 8; j++) g_p[(row0 + w * 8 + j) * 32 + c] = acc[j];
}

// fused: CSR gather + MLP + ReLU + spread BN stats
__global__ void k_mlp(int layer, const float* __restrict__ ba, const float* __restrict__ Wb,
                      const float* __restrict__ bb) {
    __shared__ float us[64][33];
    __shared__ float ws[32][33];
    __shared__ float r1[8][32];
    __shared__ float r2[8][32];
    __shared__ float bsh[32], bbsh[32];
    int tid = threadIdx.x;
    int lane = tid & 31, wid = tid >> 5;
    int row0 = blockIdx.x * 64;
    if (tid < 32) { bsh[tid] = ba[tid]; bbsh[tid] = bb[tid]; }
    for (int i = tid; i < 1024; i += 256) ws[i >> 5][i & 31] = Wb[i];
    __syncthreads();
    const float4* p4 = (const float4*)g_p;
    int eg = lane >> 3;
    int q = lane & 7;
    for (int nn = wid; nn < 64; nn += 8) {
        int node = row0 + nn;
        float4 a0 = make_float4(0.f, 0.f, 0.f, 0.f);
        float4 a1 = a0, a2 = a0, a3 = a0;
        if (eg == 0) a0 = p4[node * 8 + q];
        int i = g_off[node], ib = g_off[node + 1];
        for (; i + 16 <= ib; i += 16) {
            int s0 = g_srcl[i + eg];
            int s1 = g_srcl[i + 4 + eg];
            int s2 = g_srcl[i + 8 + eg];
            int s3 = g_srcl[i + 12 + eg];
            float4 v0 = p4[s0 * 8 + q];
            float4 v1 = p4[s1 * 8 + q];
            float4 v2 = p4[s2 * 8 + q];
            float4 v3 = p4[s3 * 8 + q];
            f4add(a0, v0);
            f4add(a1, v1);
            f4add(a2, v2);
            f4add(a3, v3);
        }
        for (; i + 4 <= ib; i += 4) f4add(a1, p4[g_srcl[i + eg] * 8 + q]);
        if (eg < ib - i) f4add(a2, p4[g_srcl[i + eg] * 8 + q]);
        f4add(a0, a1);
        f4add(a2, a3);
        f4add(a0, a2);
#pragma unroll
        for (int off = 8; off <= 16; off <<= 1) {
            a0.x += __shfl_xor_sync(0xffffffffu, a0.x, off);
            a0.y += __shfl_xor_sync(0xffffffffu, a0.y, off);
            a0.z += __shfl_xor_sync(0xffffffffu, a0.z, off);
            a0.w += __shfl_xor_sync(0xffffffffu, a0.w, off);
        }
        if (eg == 0) {
            us[nn][q * 4 + 0] = fmaxf(a0.x + bsh[q * 4 + 0], 0.f);
            us[nn][q * 4 + 1] = fmaxf(a0.y + bsh[q * 4 + 1], 0.f);
            us[nn][q * 4 + 2] = fmaxf(a0.z + bsh[q * 4 + 2], 0.f);
            us[nn][q * 4 + 3] = fmaxf(a0.w + bsh[q * 4 + 3], 0.f);
        }
    }
    __syncthreads();
    int c = lane, w = wid;
    float acc[8];
#pragma unroll
    for (int j = 0; j < 8; j++) acc[j] = bbsh[c];
#pragma unroll
    for (int k = 0; k < 32; k++) {
        float wv = ws[k][c];
#pragma unroll
        for (int j = 0; j < 8; j++) acc[j] += us[w * 8 + j][k] * wv;
    }
    float s1 = 0.f, s2 = 0.f;
#pragma unroll
    for (int j = 0; j < 8; j++) {
        float v = fmaxf(acc[j], 0.f);
        g_y[(row0 + w * 8 + j) * 32 + c] = v;
        s1 += v;
        s2 += v * v;
    }
    r1[w][c] = s1;
    r2[w][c] = s2;
    __syncthreads();
    if (w == 0) {
        float a = 0.f, b2 = 0.f;
#pragma unroll
        for (int qq = 0; qq < 8; qq++) { a += r1[qq][c]; b2 += r2[qq][c]; }
        atomicAdd(&g_stats[layer * SSLOT + c * SSTR], a);
        atomicAdd(&g_stats[layer * SSLOT + 64 * SSTR + c * SSTR], b2);
    }
}

// global add pool
__global__ void k_pool(const int* __restrict__ batch, const float* __restrict__ gamma,
                       const float* __restrict__ beta) {
    int tid = threadIdx.x;
    int lane = tid & 31;
    int gwarp = blockIdx.x * 8 + (tid >> 5);
    int q = lane & 7, sub = lane >> 3;
    int base = gwarp * 32;
    float s[4], t[4];
#pragma unroll
    for (int c = 0; c < 4; c++) {
        int d = q * 4 + c;
        float m = g_stats[4 * SSLOT + d * SSTR] * (1.f / Nn);
        float vv = g_stats[4 * SSLOT + 64 * SSTR + d * SSTR] * (1.f / Nn) - m * m;
        s[c] = gamma[d] * rsqrtf(vv + 1e-5f);
        t[c] = beta[d] - m * s[c];
    }
    const float4* y4 = (const float4*)g_y;
    float4 acc = make_float4(0.f, 0.f, 0.f, 0.f);
    int cur = batch[base + sub];
#pragma unroll 2
    for (int j = 0; j < 8; j++) {
        int node = base + j * 4 + sub;
        int b = batch[node];
        float4 v = y4[node * 8 + q];
        v.x = v.x * s[0] + t[0];
        v.y = v.y * s[1] + t[1];
        v.z = v.z * s[2] + t[2];
        v.w = v.w * s[3] + t[3];
        if (b != cur) {
            atomicAdd(&g_hg[cur * 32 + q * 4 + 0], acc.x);
            atomicAdd(&g_hg[cur * 32 + q * 4 + 1], acc.y);
            atomicAdd(&g_hg[cur * 32 + q * 4 + 2], acc.z);
            atomicAdd(&g_hg[cur * 32 + q * 4 + 3], acc.w);
            acc = make_float4(0.f, 0.f, 0.f, 0.f);
            cur = b;
        }
        f4add(acc, v);
    }
    atomicAdd(&g_hg[cur * 32 + q * 4 + 0], acc.x);
    atomicAdd(&g_hg[cur * 32 + q * 4 + 1], acc.y);
    atomicAdd(&g_hg[cur * 32 + q * 4 + 2], acc.z);
    atomicAdd(&g_hg[cur * 32 + q * 4 + 3], acc.w);
}

// ---------------- high-efficiency SGEMM: BM=128, BK=16, 256 threads ----------------
template <int BN, int TN, bool PARTIAL, bool RELU>
__global__ void gemm128(const float* __restrict__ A, const float* __restrict__ W,
                        const float* __restrict__ bias, float* __restrict__ C,
                        int K, int ldc, int kChunk, float* __restrict__ part) {
    const int N = gridDim.y * BN;
    __shared__ float As[16][132];
    __shared__ float Ws[16][BN];
    int tid = threadIdx.x;
    int tx = tid & 15, ty = tid >> 4;
    int row0 = blockIdx.x * 128;
    int col0 = blockIdx.y * BN;
    int k0 = blockIdx.z * kChunk;
    int k1 = k0 + kChunk;
    if (k1 > K) k1 = K;
    float acc[8][TN];
#pragma unroll
    for (int i = 0; i < 8; i++)
#pragma unroll
        for (int j = 0; j < TN; j++) acc[i][j] = 0.f;

    int ar = tid >> 2;
    int ak = (tid & 3) * 4;
    int wr = tid >> 4;
    int wc = (tid & 15) * (BN / 16);

    for (int kb = k0; kb < k1; kb += 16) {
        const float* Ap = A + (row0 + ar) * K + kb + ak;
        float4 va = *(const float4*)Ap;
        float4 vb = *(const float4*)(Ap + 64 * K);
        As[ak + 0][ar] = va.x; As[ak + 1][ar] = va.y;
        As[ak + 2][ar] = va.z; As[ak + 3][ar] = va.w;
        As[ak + 0][ar + 64] = vb.x; As[ak + 1][ar + 64] = vb.y;
        As[ak + 2][ar + 64] = vb.z; As[ak + 3][ar + 64] = vb.w;
        const float* Wp = W + (kb + wr) * N + col0 + wc;
        if (BN == 128) {
            *(float4*)&Ws[wr][wc] = *(const float4*)Wp;
            *(float4*)&Ws[wr][wc + 4] = *(const float4*)(Wp + 4);
        } else {
            *(float4*)&Ws[wr][wc] = *(const float4*)Wp;
        }
        __syncthreads();
#pragma unroll
        for (int kk = 0; kk < 16; kk++) {
            float av[8], bv[TN];
            *(float4*)&av[0] = *(const float4*)&As[kk][ty * 8];
            *(float4*)&av[4] = *(const float4*)&As[kk][ty * 8 + 4];
            *(float4*)&bv[0] = *(const float4*)&Ws[kk][tx * 4];
            if (TN == 8) *(float4*)&bv[4] = *(const float4*)&Ws[kk][64 + tx * 4];
#pragma unroll
            for (int i = 0; i < 8; i++)
#pragma unroll
                for (int j = 0; j < TN; j++) acc[i][j] += av[i] * bv[j];
        }
        __syncthreads();
    }

    if (PARTIAL) {
        const int Mtot = gridDim.x * 128;
        float* P = part + (size_t)blockIdx.z * Mtot * N;
#pragma unroll
        for (int i = 0; i < 8; i++) {
            int r = row0 + ty * 8 + i;
            *(float4*)&P[r * N + col0 + tx * 4] = *(float4*)&acc[i][0];
            if (TN == 8)
                *(float4*)&P[r * N + col0 + 64 + tx * 4] = *(float4*)&acc[i][4];
        }
    } else {
#pragma unroll
        for (int i = 0; i < 8; i++) {
            int r = row0 + ty * 8 + i;
#pragma unroll
            for (int h = 0; h < TN / 4; h++) {
                int c = col0 + h * 64 + tx * 4;
                float4 v;
                v.x = acc[i][h * 4 + 0] + (bias ? bias[c + 0] : 0.f);
                v.y = acc[i][h * 4 + 1] + (bias ? bias[c + 1] : 0.f);
                v.z = acc[i][h * 4 + 2] + (bias ? bias[c + 2] : 0.f);
                v.w = acc[i][h * 4 + 3] + (bias ? bias[c + 3] : 0.f);
                if (RELU) {
                    v.x = fmaxf(v.x, 0.f); v.y = fmaxf(v.y, 0.f);
                    v.z = fmaxf(v.z, 0.f); v.w = fmaxf(v.w, 0.f);
                }
                *(float4*)&C[r * ldc + c] = v;
            }
        }
    }
}

// reduce xt partials (16 splits, 1024x128) into g_xc[:,128:256] with both biases
__global__ void k_reduce_xt(const float* __restrict__ b_fcxt) {
    int idx4 = blockIdx.x * 256 + threadIdx.x;   // 32768 float4s
    int i = idx4 * 4;
    int b = i >> 7, col = i & 127;
    const float4* P = (const float4*)g_part;
    float4 s = P[idx4];
#pragma unroll
    for (int k = 1; k < 16; k++) f4add(s, P[k * (Bb * 128 / 4) + idx4]);
    float4 bs = *(const float4*)&g_bias2[col];
    float4 bf = *(const float4*)&b_fcxt[col];
    s.x += bs.x + bf.x; s.y += bs.y + bf.y;
    s.z += bs.z + bf.z; s.w += bs.w + bf.w;
    *(float4*)&g_xc[b * 256 + 128 + col] = s;
}

// ---------------- small GEMM for xd (M=1024,K=32,N=128) ----------------
__global__ void gemm_xd(const float* __restrict__ A, const float* __restrict__ W,
                        const float* __restrict__ bias, float* __restrict__ C) {
    __shared__ float As[64][33];
    __shared__ float Ws[32][128];
    int tid = threadIdx.x;
    int row0 = blockIdx.x * 64;
    for (int i = tid; i < 64 * 32; i += 256) As[i >> 5][i & 31] = A[row0 * 32 + i];
    for (int i = tid; i < 32 * 128; i += 256) Ws[i >> 7][i & 127] = W[i];
    __syncthreads();
    int tx = tid & 31, ty = tid >> 5;
    float acc[8][4];
#pragma unroll
    for (int i = 0; i < 8; i++)
#pragma unroll
        for (int m = 0; m < 4; m++) acc[i][m] = 0.f;
#pragma unroll
    for (int k = 0; k < 32; k++) {
        float rw[4];
#pragma unroll
        for (int m = 0; m < 4; m++) rw[m] = Ws[k][tx + 32 * m];
#pragma unroll
        for (int i = 0; i < 8; i++) {
            float ra = As[ty * 8 + i][k];
#pragma unroll
            for (int m = 0; m < 4; m++) acc[i][m] += ra * rw[m];
        }
    }
#pragma unroll
    for (int i = 0; i < 8; i++) {
        int r = row0 + ty * 8 + i;
#pragma unroll
        for (int m = 0; m < 4; m++) {
            int c = tx + 32 * m;
            C[r * 256 + c] = fmaxf(acc[i][m] + bias[c], 0.f);
        }
    }
}

// ---------------- final head ----------------
__global__ void k_out(const float* __restrict__ b_fc2, const float* __restrict__ wout,
                      const float* __restrict__ bout, float* __restrict__ out) {
    int b = blockIdx.x, c = threadIdx.x; // 256 threads
    float s = g_part[b * 256 + c];
#pragma unroll
    for (int k = 1; k < 4; k++) s += g_part[k * (Bb * 256) + b * 256 + c];
    float v = fmaxf(s + b_fc2[c], 0.f) * wout[c];
#pragma unroll
    for (int off = 16; off; off >>= 1) v += __shfl_down_sync(0xffffffffu, v, off);
    __shared__ float ps[8];
    if ((c & 31) == 0) ps[c >> 5] = v;
    __syncthreads();
    if (c == 0) {
        float t = bout[0];
#pragma unroll
        for (int q = 0; q < 8; q++) t += ps[q];
        out[b] = t;
    }
}

// ---------------- launcher ----------------
extern "C" void kernel_launch(void* const* d_in, const int* in_sizes, int n_in,
                              void* d_out, int out_size) {
    const float* x = (const float*)d_in[0];
    const int* edge_index = (const int*)d_in[1];
    const int* batch = (const int*)d_in[2];
    const int* target = (const int*)d_in[3];
    const float* w1a = (const float*)d_in[4];
    const float* b1a = (const float*)d_in[5];
    const float* w1b = (const float*)d_in[6];
    const float* b1b = (const float*)d_in[7];
    const float* wa = (const float*)d_in[8];
    const float* ba = (const float*)d_in[9];
    const float* wb = (const float*)d_in[10];
    const float* bb = (const float*)d_in[11];
    const float* gamma = (const float*)d_in[12];
    const float* beta = (const float*)d_in[13];
    const float* w_fcxd = (const float*)d_in[14];
    const float* b_fcxd = (const float*)d_in[15];
    const float* emb = (const float*)d_in[16];
    const float* conv_w = (const float*)d_in[17];
    const float* conv_b = (const float*)d_in[18];
    const float* w_fcxt = (const float*)d_in[19];
    const float* b_fcxt = (const float*)d_in[20];
    const float* w_fc1 = (const float*)d_in[21];
    const float* b_fc1 = (const float*)d_in[22];
    const float* w_fc2 = (const float*)d_in[23];
    const float* b_fc2 = (const float*)d_in[24];
    const float* w_out = (const float*)d_in[25];
    const float* b_out = (const float*)d_in[26];
    float* out = (float*)d_out;

    float *hgP, *xcP, *f1P, *AP, *UP, *partP;
    cudaGetSymbolAddress((void**)&hgP, g_hg);
    cudaGetSymbolAddress((void**)&xcP, g_xc);
    cudaGetSymbolAddress((void**)&f1P, g_f1);
    cudaGetSymbolAddress((void**)&AP, g_A);
    cudaGetSymbolAddress((void**)&UP, g_U);
    cudaGetSymbolAddress((void**)&partP, g_part);

    cudaFuncSetAttribute(k_buildA4, cudaFuncAttributeMaxDynamicSharedMemorySize,
                         4 * ADIM * (int)sizeof(float));

    // one-time streams (fork-join capture pattern)
    static cudaStream_t s2 = 0, s3 = 0;
    static cudaEvent_t evF = 0, evJ = 0, evC = 0;
    static bool tried = false;
    static bool use2 = false;
    if (!tried) {
        tried = true;
        if (cudaStreamCreateWithFlags(&s2, cudaStreamNonBlocking) == cudaSuccess &&
            cudaStreamCreateWithFlags(&s3, cudaStreamNonBlocking) == cudaSuccess &&
            cudaEventCreateWithFlags(&evF, cudaEventDisableTiming) == cudaSuccess &&
            cudaEventCreateWithFlags(&evJ, cudaEventDisableTiming) == cudaSuccess &&
            cudaEventCreateWithFlags(&evC, cudaEventDisableTiming) == cudaSuccess) {
            use2 = true;
        }
    }
    cudaStream_t st2 = use2 ? s2 : (cudaStream_t)0;
    cudaStream_t st3 = use2 ? s3 : (cudaStream_t)0;

    k_init<<<256, 256>>>();

    if (use2) {
        cudaEventRecord(evF, 0);
        cudaStreamWaitEvent(st2, evF, 0);
        cudaStreamWaitEvent(st3, evF, 0);
    }

    // ---- stream 3: privatized CSR build (overlaps proj78 + protein) ----
    k_hist<<<Ee / 1024, 256, 0, st3>>>(edge_index);
    k_tot<<<64, 1024, 0, st3>>>();
    k_scan<<<1, 1024, 0, st3>>>();
    k_base<<<64, 1024, 0, st3>>>();
    k_fill<<<Ee / 1024, 256, 0, st3>>>(edge_index);
    if (use2) cudaEventRecord(evC, st3);

    // ---- stream 0: GIN chain ----
    k_proj78<<<Nn / 64, 256>>>(x, w1a);
    if (use2) cudaStreamWaitEvent(0, evC, 0);
    k_mlp<<<Nn / 64, 256>>>(0, b1a, w1b, b1b);
    for (int l = 0; l < 4; l++) {
        k_proj32<<<Nn / 64, 256>>>(l, gamma + l * 32, beta + l * 32, wa + l * 1024);
        k_mlp<<<Nn / 64, 256>>>(l + 1, ba + l * 32, wb + l * 1024, bb + l * 32);
    }
    k_pool<<<Nn / 256, 256>>>(batch, gamma + 128, beta + 128);
    gemm_xd<<<16, 256>>>(hgP, w_fcxd, b_fcxd, xcP);

    // ---- stream 2: protein branch + xt GEMM (concurrent) ----
    k_transpose<<<NFIL, 256, 0, st2>>>(conv_w);
    k_buildA4<<<Bb / 4, 256, 4 * ADIM * sizeof(float), st2>>>(target);
    k_buildU<<<dim3(NFIL, VOCAB), 128, 0, st2>>>(emb, w_fcxt);
    k_bias2<<<NFIL, 128, 0, st2>>>(w_fcxt, conv_b);
    gemm128<128, 8, true, false><<<dim3(8, 1, 16), 256, 0, st2>>>(
        AP, UP, nullptr, nullptr, ADIM, 0, 416, partP);
    k_reduce_xt<<<128, 256, 0, st2>>>(b_fcxt);

    if (use2) {
        cudaEventRecord(evJ, st2);
        cudaStreamWaitEvent(0, evJ, 0);
    }

    // ---- joint head ----
    gemm128<64, 4, false, true><<<dim3(8, 16, 1), 256>>>(
        xcP, w_fc1, b_fc1, f1P, 256, 1024, 256, nullptr);
    gemm128<64, 4, true, false><<<dim3(8, 4, 4), 256>>>(
        f1P, w_fc2, nullptr, nullptr, 1024, 0, 256, partP);
    k_out<<<Bb, 256>>>(b_fc2, w_out, b_out, out);
}

// round 13
// speedup vs baseline: 1.0557x; 1.0233x over previous
#include <cuda_runtime.h>

#define Nn 65536
#define Ee 2097152
#define Bb 1024
#define FXDIM 78
#define DIM 32
#define EMBD 128
#define VOCAB 26
#define PLENN 1000
#define KSZ 8
#define CLENN 121
#define NFIL 32
#define ADIM 6656   /* VOCAB * NFIL * KSZ */
#define A4 1664     /* ADIM/4 */
#define OUTDIM 128
#define SSTR 64          /* stats stride in floats (256B) to spread atomics */
#define SSLOT (2 * 64 * SSTR)   /* floats per layer slot */

// ---------------- scratch (device globals; no allocations) ----------------
__device__ __align__(16) float g_p[Nn * DIM];
__device__ __align__(16) float g_y[Nn * DIM];
__device__ float g_stats[5 * SSLOT];
__device__ float g_hg[Bb * DIM];
__device__ __align__(16) float g_xc[Bb * 256];    // [xd | xt]
__device__ __align__(16) float g_f1[Bb * 1024];
__device__ __align__(16) float g_Wt[PLENN * 256]; // conv_w transposed to [p][f*8+k]
__device__ __align__(16) float g_A[Bb * ADIM];
__device__ __align__(16) float g_U[ADIM * OUTDIM];
__device__ __align__(16) float g_bias2[OUTDIM];
__device__ __align__(16) float g_part[16 * 1024 * 128];   // split-K partials (8 MB)
// CSR scratch (8-way privatized histogram + hierarchical scan)
__device__ __align__(16) int g_hist8[8 * Nn];
__device__ __align__(16) int g_base8[8 * Nn];
__device__ __align__(16) int g_off[Nn + 4];
__device__ int g_bsum[64];
__device__ int g_bbase[64];
__device__ __align__(16) int g_srcl[Ee];

__device__ __forceinline__ void f4add(float4& a, const float4& b) {
    a.x += b.x; a.y += b.y; a.z += b.z; a.w += b.w;
}

// ---------------- init ----------------
__global__ void k_init() {
    int i = blockIdx.x * 256 + threadIdx.x;   // 65536 threads
    int4* h4 = (int4*)g_hist8;                // 131072 int4s
    h4[i * 2 + 0] = make_int4(0, 0, 0, 0);
    h4[i * 2 + 1] = make_int4(0, 0, 0, 0);
    if (i < Bb * DIM) g_hg[i] = 0.f;
    if (i < 5 * SSLOT) g_stats[i] = 0.f;
    if (i < OUTDIM) g_bias2[i] = 0.f;
}

// ---------------- CSR build (8-way privatized, hierarchical scan) ----------------
__global__ void k_hist(const int* __restrict__ ei) {
    int e4 = blockIdx.x * 256 + threadIdx.x;
    int* H = g_hist8 + (blockIdx.x & 7) * Nn;
    int4 d = ((const int4*)(ei + Ee))[e4];
    atomicAdd(&H[d.x], 1);
    atomicAdd(&H[d.y], 1);
    atomicAdd(&H[d.z], 1);
    atomicAdd(&H[d.w], 1);
}

// phase 1: per-node totals + block-wide exclusive scan; grid 64, block 1024
__global__ void k_tot() {
    __shared__ int ws[32];
    int t = threadIdx.x, lane = t & 31, wid = t >> 5;
    int n = blockIdx.x * 1024 + t;
    int s = 0;
#pragma unroll
    for (int c = 0; c < 8; c++) s += g_hist8[c * Nn + n];
    int v = s;
#pragma unroll
    for (int off = 1; off < 32; off <<= 1) {
        int u = __shfl_up_sync(0xffffffffu, v, off);
        if (lane >= off) v += u;
    }
    if (lane == 31) ws[wid] = v;
    __syncthreads();
    if (wid == 0) {
        int w = ws[lane];
#pragma unroll
        for (int off = 1; off < 32; off <<= 1) {
            int u = __shfl_up_sync(0xffffffffu, w, off);
            if (lane >= off) w += u;
        }
        ws[lane] = w;
    }
    __syncthreads();
    int excl = v - s + (wid ? ws[wid - 1] : 0);
    g_off[n] = excl;   // local (within-block) exclusive prefix, finalized in k_base
    if (t == 1023) g_bsum[blockIdx.x] = excl + s;
}

// phase 2: one warp scans 64 block sums -> exclusive bases
__global__ void k_bscan() {
    int lane = threadIdx.x;   // 32 threads
    int a = g_bsum[lane];
    int b = g_bsum[lane + 32];
    int va = a;
#pragma unroll
    for (int off = 1; off < 32; off <<= 1) {
        int u = __shfl_up_sync(0xffffffffu, va, off);
        if (lane >= off) va += u;
    }
    int totA = __shfl_sync(0xffffffffu, va, 31);
    int vb = b;
#pragma unroll
    for (int off = 1; off < 32; off <<= 1) {
        int u = __shfl_up_sync(0xffffffffu, vb, off);
        if (lane >= off) vb += u;
    }
    g_bbase[lane] = va - a;
    g_bbase[lane + 32] = totA + vb - b;
    if (lane == 0) g_off[Nn] = Ee;
}

// phase 3: finalize offsets + per-copy bases; grid 64, block 1024
__global__ void k_base() {
    int t = threadIdx.x;
    int n = blockIdx.x * 1024 + t;
    int off = g_off[n] + g_bbase[blockIdx.x];
    g_off[n] = off;
    int run = off;
#pragma unroll
    for (int c = 0; c < 8; c++) {
        g_base8[c * Nn + n] = run;
        run += g_hist8[c * Nn + n];
    }
}

__global__ void k_fill(const int* __restrict__ ei) {
    int e4 = blockIdx.x * 256 + threadIdx.x;
    int* B = g_base8 + (blockIdx.x & 7) * Nn;   // same copy mapping as k_hist
    int4 sv = ((const int4*)ei)[e4];
    int4 dv = ((const int4*)(ei + Ee))[e4];
    int s0 = atomicAdd(&B[dv.x], 1); g_srcl[s0] = sv.x;
    int s1 = atomicAdd(&B[dv.y], 1); g_srcl[s1] = sv.y;
    int s2 = atomicAdd(&B[dv.z], 1); g_srcl[s2] = sv.z;
    int s3 = atomicAdd(&B[dv.w], 1); g_srcl[s3] = sv.w;
}

// ---------------- protein branch ----------------
__global__ void k_transpose(const float* __restrict__ conv_w) {
    int f = blockIdx.x;
    for (int i = threadIdx.x; i < PLENN * KSZ; i += 256) {
        int p = i >> 3, k = i & 7;
        g_Wt[p * 256 + f * 8 + k] = conv_w[f * PLENN * KSZ + i];
    }
}

__global__ void k_buildA4(const int* __restrict__ target) {
    extern __shared__ float4 sA4[];
    int tid = threadIdx.x;
    int b0 = blockIdx.x * 4;
    int pg = tid >> 6;
    int col4 = tid & 63;
    for (int i = tid; i < 4 * A4; i += 256) sA4[i] = make_float4(0.f, 0.f, 0.f, 0.f);
    __syncthreads();
    const float4* Wt4 = (const float4*)g_Wt;
    const int* tp = target + (b0 + pg) * PLENN;
    int pbase = pg * A4;
    for (int p = 0; p < PLENN; p += 2) {
        int va = tp[p], vb = tp[p + 1];
        float4 w0 = Wt4[p * 64 + col4];
        float4 w1 = Wt4[(p + 1) * 64 + col4];
        int ia = pbase + va * 64 + col4;
        float4 Aa = sA4[ia]; f4add(Aa, w0); sA4[ia] = Aa;
        int ib = pbase + vb * 64 + col4;
        float4 Ab = sA4[ib]; f4add(Ab, w1); sA4[ib] = Ab;
    }
    __syncthreads();
    float4* gA4 = (float4*)g_A;
    for (int j = 0; j < 4; j++)
        for (int i = tid; i < A4; i += 256)
            gA4[(b0 + j) * A4 + i] = sA4[j * A4 + i];
}

__global__ void k_buildU(const float* __restrict__ emb, const float* __restrict__ wfcxt) {
    __shared__ float se[EMBD];
    int f = blockIdx.x, v = blockIdx.y, o = threadIdx.x;
    se[o] = emb[v * EMBD + o];
    __syncthreads();
    float acc[KSZ];
#pragma unroll
    for (int k = 0; k < KSZ; k++) acc[k] = 0.f;
    const float* wf = wfcxt + f * CLENN * OUTDIM + o;
#pragma unroll 4
    for (int t = 0; t < CLENN; t++) {
        float wv = wf[t * OUTDIM];
#pragma unroll
        for (int k = 0; k < KSZ; k++) acc[k] += se[t + k] * wv;
    }
#pragma unroll
    for (int k = 0; k < KSZ; k++)
        g_U[(v * 256 + f * 8 + k) * OUTDIM + o] = acc[k];
}

__global__ void k_bias2(const float* __restrict__ wfcxt, const float* __restrict__ conv_b) {
    int f = blockIdx.x, o = threadIdx.x; // 128 threads
    float s = 0.f;
    for (int t = 0; t < CLENN; t++) s += wfcxt[(f * CLENN + t) * OUTDIM + o];
    atomicAdd(&g_bias2[o], s * conv_b[f]);
}

// ---------------- GIN layers ----------------
__global__ void k_proj78(const float* __restrict__ x, const float* __restrict__ W) {
    __shared__ float xs[64][80];
    __shared__ float ws[78][33];
    int tid = threadIdx.x;
    int row0 = blockIdx.x * 64;
    const float* xb = x + row0 * FXDIM;
    for (int i = tid; i < 64 * FXDIM; i += 256) xs[i / FXDIM][i % FXDIM] = xb[i];
    for (int i = tid; i < FXDIM * 32; i += 256) ws[i >> 5][i & 31] = W[i];
    __syncthreads();
    int c = tid & 31, w = tid >> 5;
    float acc[8];
#pragma unroll
    for (int j = 0; j < 8; j++) acc[j] = 0.f;
    for (int k = 0; k < FXDIM; k++) {
        float wv = ws[k][c];
#pragma unroll
        for (int j = 0; j < 8; j++) acc[j] += xs[w * 8 + j][k] * wv;
    }
#pragma unroll
    for (int j = 0; j < 8; j++) g_p[(row0 + w * 8 + j) * 32 + c] = acc[j];
}

__global__ void k_proj32(int slot, const float* __restrict__ gamma,
                         const float* __restrict__ beta, const float* __restrict__ W) {
    __shared__ float xs[64][33];
    __shared__ float ws[32][33];
    __shared__ float sa[64];
    int tid = threadIdx.x;
    int row0 = blockIdx.x * 64;
    if (tid < 32) {
        float m = g_stats[slot * SSLOT + tid * SSTR] * (1.f / Nn);
        float v = g_stats[slot * SSLOT + 64 * SSTR + tid * SSTR] * (1.f / Nn) - m * m;
        float s = gamma[tid] * rsqrtf(v + 1e-5f);
        sa[tid] = s;
        sa[32 + tid] = beta[tid] - m * s;
    }
    __syncthreads();
    const float4* y4 = (const float4*)g_y;
    for (int i = tid; i < 512; i += 256) {
        int r = i >> 3, q = i & 7;
        float4 v = y4[(row0 + r) * 8 + q];
        xs[r][q * 4 + 0] = v.x * sa[q * 4 + 0] + sa[32 + q * 4 + 0];
        xs[r][q * 4 + 1] = v.y * sa[q * 4 + 1] + sa[32 + q * 4 + 1];
        xs[r][q * 4 + 2] = v.z * sa[q * 4 + 2] + sa[32 + q * 4 + 2];
        xs[r][q * 4 + 3] = v.w * sa[q * 4 + 3] + sa[32 + q * 4 + 3];
    }
    for (int i = tid; i < 1024; i += 256) ws[i >> 5][i & 31] = W[i];
    __syncthreads();
    int c = tid & 31, w = tid >> 5;
    float acc[8];
#pragma unroll
    for (int j = 0; j < 8; j++) acc[j] = 0.f;
#pragma unroll
    for (int k = 0; k < 32; k++) {
        float wv = ws[k][c];
#pragma unroll
        for (int j = 0; j < 8; j++) acc[j] += xs[w * 8 + j][k] * wv;
    }
#pragma unroll
    for (int j = 0; j < 8; j++) g_p[(row0 + w * 8 + j) * 32 + c] = acc[j];
}

// fused: CSR gather + MLP + ReLU + spread BN stats
__global__ void k_mlp(int layer, const float* __restrict__ ba, const float* __restrict__ Wb,
                      const float* __restrict__ bb) {
    __shared__ float us[64][33];
    __shared__ float ws[32][33];
    __shared__ float r1[8][32];
    __shared__ float r2[8][32];
    __shared__ float bsh[32], bbsh[32];
    int tid = threadIdx.x;
    int lane = tid & 31, wid = tid >> 5;
    int row0 = blockIdx.x * 64;
    if (tid < 32) { bsh[tid] = ba[tid]; bbsh[tid] = bb[tid]; }
    for (int i = tid; i < 1024; i += 256) ws[i >> 5][i & 31] = Wb[i];
    __syncthreads();
    const float4* p4 = (const float4*)g_p;
    int eg = lane >> 3;
    int q = lane & 7;
    for (int nn = wid; nn < 64; nn += 8) {
        int node = row0 + nn;
        float4 a0 = make_float4(0.f, 0.f, 0.f, 0.f);
        float4 a1 = a0, a2 = a0, a3 = a0;
        if (eg == 0) a0 = p4[node * 8 + q];
        int i = g_off[node], ib = g_off[node + 1];
        for (; i + 16 <= ib; i += 16) {
            int s0 = g_srcl[i + eg];
            int s1 = g_srcl[i + 4 + eg];
            int s2 = g_srcl[i + 8 + eg];
            int s3 = g_srcl[i + 12 + eg];
            float4 v0 = p4[s0 * 8 + q];
            float4 v1 = p4[s1 * 8 + q];
            float4 v2 = p4[s2 * 8 + q];
            float4 v3 = p4[s3 * 8 + q];
            f4add(a0, v0);
            f4add(a1, v1);
            f4add(a2, v2);
            f4add(a3, v3);
        }
        for (; i + 4 <= ib; i += 4) f4add(a1, p4[g_srcl[i + eg] * 8 + q]);
        if (eg < ib - i) f4add(a2, p4[g_srcl[i + eg] * 8 + q]);
        f4add(a0, a1);
        f4add(a2, a3);
        f4add(a0, a2);
#pragma unroll
        for (int off = 8; off <= 16; off <<= 1) {
            a0.x += __shfl_xor_sync(0xffffffffu, a0.x, off);
            a0.y += __shfl_xor_sync(0xffffffffu, a0.y, off);
            a0.z += __shfl_xor_sync(0xffffffffu, a0.z, off);
            a0.w += __shfl_xor_sync(0xffffffffu, a0.w, off);
        }
        if (eg == 0) {
            us[nn][q * 4 + 0] = fmaxf(a0.x + bsh[q * 4 + 0], 0.f);
            us[nn][q * 4 + 1] = fmaxf(a0.y + bsh[q * 4 + 1], 0.f);
            us[nn][q * 4 + 2] = fmaxf(a0.z + bsh[q * 4 + 2], 0.f);
            us[nn][q * 4 + 3] = fmaxf(a0.w + bsh[q * 4 + 3], 0.f);
        }
    }
    __syncthreads();
    int c = lane, w = wid;
    float acc[8];
#pragma unroll
    for (int j = 0; j < 8; j++) acc[j] = bbsh[c];
#pragma unroll
    for (int k = 0; k < 32; k++) {
        float wv = ws[k][c];
#pragma unroll
        for (int j = 0; j < 8; j++) acc[j] += us[w * 8 + j][k] * wv;
    }
    float s1 = 0.f, s2 = 0.f;
#pragma unroll
    for (int j = 0; j < 8; j++) {
        float v = fmaxf(acc[j], 0.f);
        g_y[(row0 + w * 8 + j) * 32 + c] = v;
        s1 += v;
        s2 += v * v;
    }
    r1[w][c] = s1;
    r2[w][c] = s2;
    __syncthreads();
    if (w == 0) {
        float a = 0.f, b2 = 0.f;
#pragma unroll
        for (int qq = 0; qq < 8; qq++) { a += r1[qq][c]; b2 += r2[qq][c]; }
        atomicAdd(&g_stats[layer * SSLOT + c * SSTR], a);
        atomicAdd(&g_stats[layer * SSLOT + 64 * SSTR + c * SSTR], b2);
    }
}

// global add pool
__global__ void k_pool(const int* __restrict__ batch, const float* __restrict__ gamma,
                       const float* __restrict__ beta) {
    int tid = threadIdx.x;
    int lane = tid & 31;
    int gwarp = blockIdx.x * 8 + (tid >> 5);
    int q = lane & 7, sub = lane >> 3;
    int base = gwarp * 32;
    float s[4], t[4];
#pragma unroll
    for (int c = 0; c < 4; c++) {
        int d = q * 4 + c;
        float m = g_stats[4 * SSLOT + d * SSTR] * (1.f / Nn);
        float vv = g_stats[4 * SSLOT + 64 * SSTR + d * SSTR] * (1.f / Nn) - m * m;
        s[c] = gamma[d] * rsqrtf(vv + 1e-5f);
        t[c] = beta[d] - m * s[c];
    }
    const float4* y4 = (const float4*)g_y;
    float4 acc = make_float4(0.f, 0.f, 0.f, 0.f);
    int cur = batch[base + sub];
#pragma unroll 2
    for (int j = 0; j < 8; j++) {
        int node = base + j * 4 + sub;
        int b = batch[node];
        float4 v = y4[node * 8 + q];
        v.x = v.x * s[0] + t[0];
        v.y = v.y * s[1] + t[1];
        v.z = v.z * s[2] + t[2];
        v.w = v.w * s[3] + t[3];
        if (b != cur) {
            atomicAdd(&g_hg[cur * 32 + q * 4 + 0], acc.x);
            atomicAdd(&g_hg[cur * 32 + q * 4 + 1], acc.y);
            atomicAdd(&g_hg[cur * 32 + q * 4 + 2], acc.z);
            atomicAdd(&g_hg[cur * 32 + q * 4 + 3], acc.w);
            acc = make_float4(0.f, 0.f, 0.f, 0.f);
            cur = b;
        }
        f4add(acc, v);
    }
    atomicAdd(&g_hg[cur * 32 + q * 4 + 0], acc.x);
    atomicAdd(&g_hg[cur * 32 + q * 4 + 1], acc.y);
    atomicAdd(&g_hg[cur * 32 + q * 4 + 2], acc.z);
    atomicAdd(&g_hg[cur * 32 + q * 4 + 3], acc.w);
}

// ---------------- high-efficiency SGEMM: BM=128, BK=16, 256 threads ----------------
template <int BN, int TN, bool PARTIAL, bool RELU>
__global__ void gemm128(const float* __restrict__ A, const float* __restrict__ W,
                        const float* __restrict__ bias, float* __restrict__ C,
                        int K, int ldc, int kChunk, float* __restrict__ part) {
    const int N = gridDim.y * BN;
    __shared__ float As[16][132];
    __shared__ float Ws[16][BN];
    int tid = threadIdx.x;
    int tx = tid & 15, ty = tid >> 4;
    int row0 = blockIdx.x * 128;
    int col0 = blockIdx.y * BN;
    int k0 = blockIdx.z * kChunk;
    int k1 = k0 + kChunk;
    if (k1 > K) k1 = K;
    float acc[8][TN];
#pragma unroll
    for (int i = 0; i < 8; i++)
#pragma unroll
        for (int j = 0; j < TN; j++) acc[i][j] = 0.f;

    int ar = tid >> 2;
    int ak = (tid & 3) * 4;
    int wr = tid >> 4;
    int wc = (tid & 15) * (BN / 16);

    for (int kb = k0; kb < k1; kb += 16) {
        const float* Ap = A + (row0 + ar) * K + kb + ak;
        float4 va = *(const float4*)Ap;
        float4 vb = *(const float4*)(Ap + 64 * K);
        As[ak + 0][ar] = va.x; As[ak + 1][ar] = va.y;
        As[ak + 2][ar] = va.z; As[ak + 3][ar] = va.w;
        As[ak + 0][ar + 64] = vb.x; As[ak + 1][ar + 64] = vb.y;
        As[ak + 2][ar + 64] = vb.z; As[ak + 3][ar + 64] = vb.w;
        const float* Wp = W + (kb + wr) * N + col0 + wc;
        if (BN == 128) {
            *(float4*)&Ws[wr][wc] = *(const float4*)Wp;
            *(float4*)&Ws[wr][wc + 4] = *(const float4*)(Wp + 4);
        } else {
            *(float4*)&Ws[wr][wc] = *(const float4*)Wp;
        }
        __syncthreads();
#pragma unroll
        for (int kk = 0; kk < 16; kk++) {
            float av[8], bv[TN];
            *(float4*)&av[0] = *(const float4*)&As[kk][ty * 8];
            *(float4*)&av[4] = *(const float4*)&As[kk][ty * 8 + 4];
            *(float4*)&bv[0] = *(const float4*)&Ws[kk][tx * 4];
            if (TN == 8) *(float4*)&bv[4] = *(const float4*)&Ws[kk][64 + tx * 4];
#pragma unroll
            for (int i = 0; i < 8; i++)
#pragma unroll
                for (int j = 0; j < TN; j++) acc[i][j] += av[i] * bv[j];
        }
        __syncthreads();
    }

    if (PARTIAL) {
        const int Mtot = gridDim.x * 128;
        float* P = part + (size_t)blockIdx.z * Mtot * N;
#pragma unroll
        for (int i = 0; i < 8; i++) {
            int r = row0 + ty * 8 + i;
            *(float4*)&P[r * N + col0 + tx * 4] = *(float4*)&acc[i][0];
            if (TN == 8)
                *(float4*)&P[r * N + col0 + 64 + tx * 4] = *(float4*)&acc[i][4];
        }
    } else {
#pragma unroll
        for (int i = 0; i < 8; i++) {
            int r = row0 + ty * 8 + i;
#pragma unroll
            for (int h = 0; h < TN / 4; h++) {
                int c = col0 + h * 64 + tx * 4;
                float4 v;
                v.x = acc[i][h * 4 + 0] + (bias ? bias[c + 0] : 0.f);
                v.y = acc[i][h * 4 + 1] + (bias ? bias[c + 1] : 0.f);
                v.z = acc[i][h * 4 + 2] + (bias ? bias[c + 2] : 0.f);
                v.w = acc[i][h * 4 + 3] + (bias ? bias[c + 3] : 0.f);
                if (RELU) {
                    v.x = fmaxf(v.x, 0.f); v.y = fmaxf(v.y, 0.f);
                    v.z = fmaxf(v.z, 0.f); v.w = fmaxf(v.w, 0.f);
                }
                *(float4*)&C[r * ldc + c] = v;
            }
        }
    }
}

// reduce xt partials (16 splits, 1024x128) into g_xc[:,128:256] with both biases
__global__ void k_reduce_xt(const float* __restrict__ b_fcxt) {
    int idx4 = blockIdx.x * 256 + threadIdx.x;   // 32768 float4s
    int i = idx4 * 4;
    int b = i >> 7, col = i & 127;
    const float4* P = (const float4*)g_part;
    float4 s = P[idx4];
#pragma unroll
    for (int k = 1; k < 16; k++) f4add(s, P[k * (Bb * 128 / 4) + idx4]);
    float4 bs = *(const float4*)&g_bias2[col];
    float4 bf = *(const float4*)&b_fcxt[col];
    s.x += bs.x + bf.x; s.y += bs.y + bf.y;
    s.z += bs.z + bf.z; s.w += bs.w + bf.w;
    *(float4*)&g_xc[b * 256 + 128 + col] = s;
}

// ---------------- small GEMM for xd (M=1024,K=32,N=128) ----------------
__global__ void gemm_xd(const float* __restrict__ A, const float* __restrict__ W,
                        const float* __restrict__ bias, float* __restrict__ C) {
    __shared__ float As[64][33];
    __shared__ float Ws[32][128];
    int tid = threadIdx.x;
    int row0 = blockIdx.x * 64;
    for (int i = tid; i < 64 * 32; i += 256) As[i >> 5][i & 31] = A[row0 * 32 + i];
    for (int i = tid; i < 32 * 128; i += 256) Ws[i >> 7][i & 127] = W[i];
    __syncthreads();
    int tx = tid & 31, ty = tid >> 5;
    float acc[8][4];
#pragma unroll
    for (int i = 0; i < 8; i++)
#pragma unroll
        for (int m = 0; m < 4; m++) acc[i][m] = 0.f;
#pragma unroll
    for (int k = 0; k < 32; k++) {
        float rw[4];
#pragma unroll
        for (int m = 0; m < 4; m++) rw[m] = Ws[k][tx + 32 * m];
#pragma unroll
        for (int i = 0; i < 8; i++) {
            float ra = As[ty * 8 + i][k];
#pragma unroll
            for (int m = 0; m < 4; m++) acc[i][m] += ra * rw[m];
        }
    }
#pragma unroll
    for (int i = 0; i < 8; i++) {
        int r = row0 + ty * 8 + i;
#pragma unroll
        for (int m = 0; m < 4; m++) {
            int c = tx + 32 * m;
            C[r * 256 + c] = fmaxf(acc[i][m] + bias[c], 0.f);
        }
    }
}

// ---------------- final head ----------------
__global__ void k_out(const float* __restrict__ b_fc2, const float* __restrict__ wout,
                      const float* __restrict__ bout, float* __restrict__ out) {
    int b = blockIdx.x, c = threadIdx.x; // 256 threads
    float s = g_part[b * 256 + c];
#pragma unroll
    for (int k = 1; k < 4; k++) s += g_part[k * (Bb * 256) + b * 256 + c];
    float v = fmaxf(s + b_fc2[c], 0.f) * wout[c];
#pragma unroll
    for (int off = 16; off; off >>= 1) v += __shfl_down_sync(0xffffffffu, v, off);
    __shared__ float ps[8];
    if ((c & 31) == 0) ps[c >> 5] = v;
    __syncthreads();
    if (c == 0) {
        float t = bout[0];
#pragma unroll
        for (int q = 0; q < 8; q++) t += ps[q];
        out[b] = t;
    }
}

// ---------------- launcher ----------------
extern "C" void kernel_launch(void* const* d_in, const int* in_sizes, int n_in,
                              void* d_out, int out_size) {
    const float* x = (const float*)d_in[0];
    const int* edge_index = (const int*)d_in[1];
    const int* batch = (const int*)d_in[2];
    const int* target = (const int*)d_in[3];
    const float* w1a = (const float*)d_in[4];
    const float* b1a = (const float*)d_in[5];
    const float* w1b = (const float*)d_in[6];
    const float* b1b = (const float*)d_in[7];
    const float* wa = (const float*)d_in[8];
    const float* ba = (const float*)d_in[9];
    const float* wb = (const float*)d_in[10];
    const float* bb = (const float*)d_in[11];
    const float* gamma = (const float*)d_in[12];
    const float* beta = (const float*)d_in[13];
    const float* w_fcxd = (const float*)d_in[14];
    const float* b_fcxd = (const float*)d_in[15];
    const float* emb = (const float*)d_in[16];
    const float* conv_w = (const float*)d_in[17];
    const float* conv_b = (const float*)d_in[18];
    const float* w_fcxt = (const float*)d_in[19];
    const float* b_fcxt = (const float*)d_in[20];
    const float* w_fc1 = (const float*)d_in[21];
    const float* b_fc1 = (const float*)d_in[22];
    const float* w_fc2 = (const float*)d_in[23];
    const float* b_fc2 = (const float*)d_in[24];
    const float* w_out = (const float*)d_in[25];
    const float* b_out = (const float*)d_in[26];
    float* out = (float*)d_out;

    float *hgP, *xcP, *f1P, *AP, *UP, *partP;
    cudaGetSymbolAddress((void**)&hgP, g_hg);
    cudaGetSymbolAddress((void**)&xcP, g_xc);
    cudaGetSymbolAddress((void**)&f1P, g_f1);
    cudaGetSymbolAddress((void**)&AP, g_A);
    cudaGetSymbolAddress((void**)&UP, g_U);
    cudaGetSymbolAddress((void**)&partP, g_part);

    cudaFuncSetAttribute(k_buildA4, cudaFuncAttributeMaxDynamicSharedMemorySize,
                         4 * ADIM * (int)sizeof(float));

    // one-time streams (fork-join capture pattern)
    static cudaStream_t s2 = 0, s3 = 0;
    static cudaEvent_t evF = 0, evJ = 0, evC = 0;
    static bool tried = false;
    static bool use2 = false;
    if (!tried) {
        tried = true;
        if (cudaStreamCreateWithFlags(&s2, cudaStreamNonBlocking) == cudaSuccess &&
            cudaStreamCreateWithFlags(&s3, cudaStreamNonBlocking) == cudaSuccess &&
            cudaEventCreateWithFlags(&evF, cudaEventDisableTiming) == cudaSuccess &&
            cudaEventCreateWithFlags(&evJ, cudaEventDisableTiming) == cudaSuccess &&
            cudaEventCreateWithFlags(&evC, cudaEventDisableTiming) == cudaSuccess) {
            use2 = true;
        }
    }
    cudaStream_t st2 = use2 ? s2 : (cudaStream_t)0;
    cudaStream_t st3 = use2 ? s3 : (cudaStream_t)0;

    k_init<<<256, 256>>>();

    if (use2) {
        cudaEventRecord(evF, 0);
        cudaStreamWaitEvent(st2, evF, 0);
        cudaStreamWaitEvent(st3, evF, 0);
    }

    // ---- stream 3: privatized CSR build with hierarchical scan ----
    k_hist<<<Ee / 1024, 256, 0, st3>>>(edge_index);
    k_tot<<<64, 1024, 0, st3>>>();
    k_bscan<<<1, 32, 0, st3>>>();
    k_base<<<64, 1024, 0, st3>>>();
    k_fill<<<Ee / 1024, 256, 0, st3>>>(edge_index);
    if (use2) cudaEventRecord(evC, st3);

    // ---- stream 0: GIN chain ----
    k_proj78<<<Nn / 64, 256>>>(x, w1a);
    if (use2) cudaStreamWaitEvent(0, evC, 0);
    k_mlp<<<Nn / 64, 256>>>(0, b1a, w1b, b1b);
    for (int l = 0; l < 4; l++) {
        k_proj32<<<Nn / 64, 256>>>(l, gamma + l * 32, beta + l * 32, wa + l * 1024);
        k_mlp<<<Nn / 64, 256>>>(l + 1, ba + l * 32, wb + l * 1024, bb + l * 32);
    }
    k_pool<<<Nn / 256, 256>>>(batch, gamma + 128, beta + 128);
    gemm_xd<<<16, 256>>>(hgP, w_fcxd, b_fcxd, xcP);

    // ---- stream 2: protein branch + xt GEMM (concurrent) ----
    k_transpose<<<NFIL, 256, 0, st2>>>(conv_w);
    k_buildA4<<<Bb / 4, 256, 4 * ADIM * sizeof(float), st2>>>(target);
    k_buildU<<<dim3(NFIL, VOCAB), 128, 0, st2>>>(emb, w_fcxt);
    k_bias2<<<NFIL, 128, 0, st2>>>(w_fcxt, conv_b);
    gemm128<128, 8, true, false><<<dim3(8, 1, 16), 256, 0, st2>>>(
        AP, UP, nullptr, nullptr, ADIM, 0, 416, partP);
    k_reduce_xt<<<128, 256, 0, st2>>>(b_fcxt);

    if (use2) {
        cudaEventRecord(evJ, st2);
        cudaStreamWaitEvent(0, evJ, 0);
    }

    // ---- joint head ----
    gemm128<64, 4, false, true><<<dim3(8, 16, 1), 256>>>(
        xcP, w_fc1, b_fc1, f1P, 256, 1024, 256, nullptr);
    gemm128<64, 4, true, false><<<dim3(8, 4, 4), 256>>>(
        f1P, w_fc2, nullptr, nullptr, 1024, 0, 256, partP);
    k_out<<<Bb, 256>>>(b_fc2, w_out, b_out, out);
}

// round 14
// speedup vs baseline: 1.0604x; 1.0045x over previous
#include <cuda_runtime.h>

#define Nn 65536
#define Ee 2097152
#define Bb 1024
#define FXDIM 78
#define DIM 32
#define EMBD 128
#define VOCAB 26
#define PLENN 1000
#define KSZ 8
#define CLENN 121
#define NFIL 32
#define ADIM 6656   /* VOCAB * NFIL * KSZ */
#define A4 1664     /* ADIM/4 */
#define OUTDIM 128
#define NCOPY 16         /* CSR privatization ways */
#define SSTR 64          /* stats stride in floats (256B) to spread atomics */
#define SSLOT (2 * 64 * SSTR)   /* floats per layer slot */

// ---------------- scratch (device globals; no allocations) ----------------
__device__ __align__(16) float g_p[Nn * DIM];
__device__ __align__(16) float g_y[Nn * DIM];
__device__ float g_stats[5 * SSLOT];
__device__ float g_hg[Bb * DIM];
__device__ __align__(16) float g_xc[Bb * 256];    // [xd | xt]
__device__ __align__(16) float g_f1[Bb * 1024];
__device__ __align__(16) float g_Wt[PLENN * 256]; // conv_w transposed to [p][f*8+k]
__device__ __align__(16) float g_A[Bb * ADIM];
__device__ __align__(16) float g_U[ADIM * OUTDIM];
__device__ __align__(16) float g_bias2[OUTDIM];
__device__ __align__(16) float g_part[16 * 1024 * 128];   // split-K partials (8 MB)
// CSR scratch (16-way privatized histogram + hierarchical scan)
__device__ __align__(16) int g_hist[NCOPY * Nn];
__device__ __align__(16) int g_baseC[NCOPY * Nn];
__device__ __align__(16) int g_off[Nn + 4];
__device__ int g_bsum[64];
__device__ int g_bbase[64];
__device__ __align__(16) int g_srcl[Ee];

__device__ __forceinline__ void f4add(float4& a, const float4& b) {
    a.x += b.x; a.y += b.y; a.z += b.z; a.w += b.w;
}

// ---------------- init ----------------
__global__ void k_init() {
    int i = blockIdx.x * 256 + threadIdx.x;   // 65536 threads
    int4* h4 = (int4*)g_hist;                 // NCOPY*Nn/4 = 262144 int4s
#pragma unroll
    for (int j = 0; j < NCOPY / 4; j++) h4[i * (NCOPY / 4) + j] = make_int4(0, 0, 0, 0);
    if (i < Bb * DIM) g_hg[i] = 0.f;
    if (i < 5 * SSLOT) g_stats[i] = 0.f;
    if (i < OUTDIM) g_bias2[i] = 0.f;
}

// ---------------- CSR build (16-way privatized, hierarchical scan) ----------------
__global__ void k_hist(const int* __restrict__ ei) {
    int e4 = blockIdx.x * 256 + threadIdx.x;
    int* H = g_hist + (blockIdx.x & (NCOPY - 1)) * Nn;
    int4 d = ((const int4*)(ei + Ee))[e4];
    atomicAdd(&H[d.x], 1);
    atomicAdd(&H[d.y], 1);
    atomicAdd(&H[d.z], 1);
    atomicAdd(&H[d.w], 1);
}

// phase 1: per-node totals + block-wide exclusive scan; grid 64, block 1024
__global__ void k_tot() {
    __shared__ int ws[32];
    int t = threadIdx.x, lane = t & 31, wid = t >> 5;
    int n = blockIdx.x * 1024 + t;
    int s = 0;
#pragma unroll
    for (int c = 0; c < NCOPY; c++) s += g_hist[c * Nn + n];
    int v = s;
#pragma unroll
    for (int off = 1; off < 32; off <<= 1) {
        int u = __shfl_up_sync(0xffffffffu, v, off);
        if (lane >= off) v += u;
    }
    if (lane == 31) ws[wid] = v;
    __syncthreads();
    if (wid == 0) {
        int w = ws[lane];
#pragma unroll
        for (int off = 1; off < 32; off <<= 1) {
            int u = __shfl_up_sync(0xffffffffu, w, off);
            if (lane >= off) w += u;
        }
        ws[lane] = w;
    }
    __syncthreads();
    int excl = v - s + (wid ? ws[wid - 1] : 0);
    g_off[n] = excl;   // local prefix, finalized in k_base
    if (t == 1023) g_bsum[blockIdx.x] = excl + s;
}

// phase 2: one warp scans 64 block sums -> exclusive bases
__global__ void k_bscan() {
    int lane = threadIdx.x;   // 32 threads
    int a = g_bsum[lane];
    int b = g_bsum[lane + 32];
    int va = a;
#pragma unroll
    for (int off = 1; off < 32; off <<= 1) {
        int u = __shfl_up_sync(0xffffffffu, va, off);
        if (lane >= off) va += u;
    }
    int totA = __shfl_sync(0xffffffffu, va, 31);
    int vb = b;
#pragma unroll
    for (int off = 1; off < 32; off <<= 1) {
        int u = __shfl_up_sync(0xffffffffu, vb, off);
        if (lane >= off) vb += u;
    }
    g_bbase[lane] = va - a;
    g_bbase[lane + 32] = totA + vb - b;
    if (lane == 0) g_off[Nn] = Ee;
}

// phase 3: finalize offsets + per-copy bases; grid 64, block 1024
__global__ void k_base() {
    int t = threadIdx.x;
    int n = blockIdx.x * 1024 + t;
    int off = g_off[n] + g_bbase[blockIdx.x];
    g_off[n] = off;
    int run = off;
#pragma unroll
    for (int c = 0; c < NCOPY; c++) {
        g_baseC[c * Nn + n] = run;
        run += g_hist[c * Nn + n];
    }
}

__global__ void k_fill(const int* __restrict__ ei) {
    int e4 = blockIdx.x * 256 + threadIdx.x;
    int* B = g_baseC + (blockIdx.x & (NCOPY - 1)) * Nn;   // same copy mapping as k_hist
    int4 sv = ((const int4*)ei)[e4];
    int4 dv = ((const int4*)(ei + Ee))[e4];
    int s0 = atomicAdd(&B[dv.x], 1); g_srcl[s0] = sv.x;
    int s1 = atomicAdd(&B[dv.y], 1); g_srcl[s1] = sv.y;
    int s2 = atomicAdd(&B[dv.z], 1); g_srcl[s2] = sv.z;
    int s3 = atomicAdd(&B[dv.w], 1); g_srcl[s3] = sv.w;
}

// ---------------- protein branch ----------------
__global__ void k_transpose(const float* __restrict__ conv_w) {
    int f = blockIdx.x;
    for (int i = threadIdx.x; i < PLENN * KSZ; i += 256) {
        int p = i >> 3, k = i & 7;
        g_Wt[p * 256 + f * 8 + k] = conv_w[f * PLENN * KSZ + i];
    }
}

__global__ void k_buildA4(const int* __restrict__ target) {
    extern __shared__ float4 sA4[];
    int tid = threadIdx.x;
    int b0 = blockIdx.x * 4;
    int pg = tid >> 6;
    int col4 = tid & 63;
    for (int i = tid; i < 4 * A4; i += 256) sA4[i] = make_float4(0.f, 0.f, 0.f, 0.f);
    __syncthreads();
    const float4* Wt4 = (const float4*)g_Wt;
    const int* tp = target + (b0 + pg) * PLENN;
    int pbase = pg * A4;
    for (int p = 0; p < PLENN; p += 2) {
        int va = tp[p], vb = tp[p + 1];
        float4 w0 = Wt4[p * 64 + col4];
        float4 w1 = Wt4[(p + 1) * 64 + col4];
        int ia = pbase + va * 64 + col4;
        float4 Aa = sA4[ia]; f4add(Aa, w0); sA4[ia] = Aa;
        int ib = pbase + vb * 64 + col4;
        float4 Ab = sA4[ib]; f4add(Ab, w1); sA4[ib] = Ab;
    }
    __syncthreads();
    float4* gA4 = (float4*)g_A;
    for (int j = 0; j < 4; j++)
        for (int i = tid; i < A4; i += 256)
            gA4[(b0 + j) * A4 + i] = sA4[j * A4 + i];
}

__global__ void k_buildU(const float* __restrict__ emb, const float* __restrict__ wfcxt) {
    __shared__ float se[EMBD];
    int f = blockIdx.x, v = blockIdx.y, o = threadIdx.x;
    se[o] = emb[v * EMBD + o];
    __syncthreads();
    float acc[KSZ];
#pragma unroll
    for (int k = 0; k < KSZ; k++) acc[k] = 0.f;
    const float* wf = wfcxt + f * CLENN * OUTDIM + o;
#pragma unroll 4
    for (int t = 0; t < CLENN; t++) {
        float wv = wf[t * OUTDIM];
#pragma unroll
        for (int k = 0; k < KSZ; k++) acc[k] += se[t + k] * wv;
    }
#pragma unroll
    for (int k = 0; k < KSZ; k++)
        g_U[(v * 256 + f * 8 + k) * OUTDIM + o] = acc[k];
}

__global__ void k_bias2(const float* __restrict__ wfcxt, const float* __restrict__ conv_b) {
    int f = blockIdx.x, o = threadIdx.x; // 128 threads
    float s = 0.f;
    for (int t = 0; t < CLENN; t++) s += wfcxt[(f * CLENN + t) * OUTDIM + o];
    atomicAdd(&g_bias2[o], s * conv_b[f]);
}

// ---------------- GIN layers ----------------
__global__ void k_proj78(const float* __restrict__ x, const float* __restrict__ W) {
    __shared__ float xs[64][80];
    __shared__ float ws[78][33];
    int tid = threadIdx.x;
    int row0 = blockIdx.x * 64;
    const float* xb = x + row0 * FXDIM;
    for (int i = tid; i < 64 * FXDIM; i += 256) xs[i / FXDIM][i % FXDIM] = xb[i];
    for (int i = tid; i < FXDIM * 32; i += 256) ws[i >> 5][i & 31] = W[i];
    __syncthreads();
    int c = tid & 31, w = tid >> 5;
    float acc[8];
#pragma unroll
    for (int j = 0; j < 8; j++) acc[j] = 0.f;
    for (int k = 0; k < FXDIM; k++) {
        float wv = ws[k][c];
#pragma unroll
        for (int j = 0; j < 8; j++) acc[j] += xs[w * 8 + j][k] * wv;
    }
#pragma unroll
    for (int j = 0; j < 8; j++) g_p[(row0 + w * 8 + j) * 32 + c] = acc[j];
}

__global__ void k_proj32(int slot, const float* __restrict__ gamma,
                         const float* __restrict__ beta, const float* __restrict__ W) {
    __shared__ float xs[64][33];
    __shared__ float ws[32][33];
    __shared__ float sa[64];
    int tid = threadIdx.x;
    int row0 = blockIdx.x * 64;
    if (tid < 32) {
        float m = g_stats[slot * SSLOT + tid * SSTR] * (1.f / Nn);
        float v = g_stats[slot * SSLOT + 64 * SSTR + tid * SSTR] * (1.f / Nn) - m * m;
        float s = gamma[tid] * rsqrtf(v + 1e-5f);
        sa[tid] = s;
        sa[32 + tid] = beta[tid] - m * s;
    }
    __syncthreads();
    const float4* y4 = (const float4*)g_y;
    for (int i = tid; i < 512; i += 256) {
        int r = i >> 3, q = i & 7;
        float4 v = y4[(row0 + r) * 8 + q];
        xs[r][q * 4 + 0] = v.x * sa[q * 4 + 0] + sa[32 + q * 4 + 0];
        xs[r][q * 4 + 1] = v.y * sa[q * 4 + 1] + sa[32 + q * 4 + 1];
        xs[r][q * 4 + 2] = v.z * sa[q * 4 + 2] + sa[32 + q * 4 + 2];
        xs[r][q * 4 + 3] = v.w * sa[q * 4 + 3] + sa[32 + q * 4 + 3];
    }
    for (int i = tid; i < 1024; i += 256) ws[i >> 5][i & 31] = W[i];
    __syncthreads();
    int c = tid & 31, w = tid >> 5;
    float acc[8];
#pragma unroll
    for (int j = 0; j < 8; j++) acc[j] = 0.f;
#pragma unroll
    for (int k = 0; k < 32; k++) {
        float wv = ws[k][c];
#pragma unroll
        for (int j = 0; j < 8; j++) acc[j] += xs[w * 8 + j][k] * wv;
    }
#pragma unroll
    for (int j = 0; j < 8; j++) g_p[(row0 + w * 8 + j) * 32 + c] = acc[j];
}

// fused: CSR gather + MLP + ReLU + spread BN stats
__global__ void k_mlp(int layer, const float* __restrict__ ba, const float* __restrict__ Wb,
                      const float* __restrict__ bb) {
    __shared__ float us[64][33];
    __shared__ float ws[32][33];
    __shared__ float r1[8][32];
    __shared__ float r2[8][32];
    __shared__ float bsh[32], bbsh[32];
    int tid = threadIdx.x;
    int lane = tid & 31, wid = tid >> 5;
    int row0 = blockIdx.x * 64;
    if (tid < 32) { bsh[tid] = ba[tid]; bbsh[tid] = bb[tid]; }
    for (int i = tid; i < 1024; i += 256) ws[i >> 5][i & 31] = Wb[i];
    __syncthreads();
    const float4* p4 = (const float4*)g_p;
    int eg = lane >> 3;
    int q = lane & 7;
    for (int nn = wid; nn < 64; nn += 8) {
        int node = row0 + nn;
        float4 a0 = make_float4(0.f, 0.f, 0.f, 0.f);
        float4 a1 = a0, a2 = a0, a3 = a0;
        if (eg == 0) a0 = p4[node * 8 + q];
        int i = g_off[node], ib = g_off[node + 1];
        for (; i + 16 <= ib; i += 16) {
            int s0 = g_srcl[i + eg];
            int s1 = g_srcl[i + 4 + eg];
            int s2 = g_srcl[i + 8 + eg];
            int s3 = g_srcl[i + 12 + eg];
            float4 v0 = p4[s0 * 8 + q];
            float4 v1 = p4[s1 * 8 + q];
            float4 v2 = p4[s2 * 8 + q];
            float4 v3 = p4[s3 * 8 + q];
            f4add(a0, v0);
            f4add(a1, v1);
            f4add(a2, v2);
            f4add(a3, v3);
        }
        for (; i + 4 <= ib; i += 4) f4add(a1, p4[g_srcl[i + eg] * 8 + q]);
        if (eg < ib - i) f4add(a2, p4[g_srcl[i + eg] * 8 + q]);
        f4add(a0, a1);
        f4add(a2, a3);
        f4add(a0, a2);
#pragma unroll
        for (int off = 8; off <= 16; off <<= 1) {
            a0.x += __shfl_xor_sync(0xffffffffu, a0.x, off);
            a0.y += __shfl_xor_sync(0xffffffffu, a0.y, off);
            a0.z += __shfl_xor_sync(0xffffffffu, a0.z, off);
            a0.w += __shfl_xor_sync(0xffffffffu, a0.w, off);
        }
        if (eg == 0) {
            us[nn][q * 4 + 0] = fmaxf(a0.x + bsh[q * 4 + 0], 0.f);
            us[nn][q * 4 + 1] = fmaxf(a0.y + bsh[q * 4 + 1], 0.f);
            us[nn][q * 4 + 2] = fmaxf(a0.z + bsh[q * 4 + 2], 0.f);
            us[nn][q * 4 + 3] = fmaxf(a0.w + bsh[q * 4 + 3], 0.f);
        }
    }
    __syncthreads();
    int c = lane, w = wid;
    float acc[8];
#pragma unroll
    for (int j = 0; j < 8; j++) acc[j] = bbsh[c];
#pragma unroll
    for (int k = 0; k < 32; k++) {
        float wv = ws[k][c];
#pragma unroll
        for (int j = 0; j < 8; j++) acc[j] += us[w * 8 + j][k] * wv;
    }
    float s1 = 0.f, s2 = 0.f;
#pragma unroll
    for (int j = 0; j < 8; j++) {
        float v = fmaxf(acc[j], 0.f);
        g_y[(row0 + w * 8 + j) * 32 + c] = v;
        s1 += v;
        s2 += v * v;
    }
    r1[w][c] = s1;
    r2[w][c] = s2;
    __syncthreads();
    if (w == 0) {
        float a = 0.f, b2 = 0.f;
#pragma unroll
        for (int qq = 0; qq < 8; qq++) { a += r1[qq][c]; b2 += r2[qq][c]; }
        atomicAdd(&g_stats[layer * SSLOT + c * SSTR], a);
        atomicAdd(&g_stats[layer * SSLOT + 64 * SSTR + c * SSTR], b2);
    }
}

// global add pool
__global__ void k_pool(const int* __restrict__ batch, const float* __restrict__ gamma,
                       const float* __restrict__ beta) {
    int tid = threadIdx.x;
    int lane = tid & 31;
    int gwarp = blockIdx.x * 8 + (tid >> 5);
    int q = lane & 7, sub = lane >> 3;
    int base = gwarp * 32;
    float s[4], t[4];
#pragma unroll
    for (int c = 0; c < 4; c++) {
        int d = q * 4 + c;
        float m = g_stats[4 * SSLOT + d * SSTR] * (1.f / Nn);
        float vv = g_stats[4 * SSLOT + 64 * SSTR + d * SSTR] * (1.f / Nn) - m * m;
        s[c] = gamma[d] * rsqrtf(vv + 1e-5f);
        t[c] = beta[d] - m * s[c];
    }
    const float4* y4 = (const float4*)g_y;
    float4 acc = make_float4(0.f, 0.f, 0.f, 0.f);
    int cur = batch[base + sub];
#pragma unroll 2
    for (int j = 0; j < 8; j++) {
        int node = base + j * 4 + sub;
        int b = batch[node];
        float4 v = y4[node * 8 + q];
        v.x = v.x * s[0] + t[0];
        v.y = v.y * s[1] + t[1];
        v.z = v.z * s[2] + t[2];
        v.w = v.w * s[3] + t[3];
        if (b != cur) {
            atomicAdd(&g_hg[cur * 32 + q * 4 + 0], acc.x);
            atomicAdd(&g_hg[cur * 32 + q * 4 + 1], acc.y);
            atomicAdd(&g_hg[cur * 32 + q * 4 + 2], acc.z);
            atomicAdd(&g_hg[cur * 32 + q * 4 + 3], acc.w);
            acc = make_float4(0.f, 0.f, 0.f, 0.f);
            cur = b;
        }
        f4add(acc, v);
    }
    atomicAdd(&g_hg[cur * 32 + q * 4 + 0], acc.x);
    atomicAdd(&g_hg[cur * 32 + q * 4 + 1], acc.y);
    atomicAdd(&g_hg[cur * 32 + q * 4 + 2], acc.z);
    atomicAdd(&g_hg[cur * 32 + q * 4 + 3], acc.w);
}

// ---------------- high-efficiency SGEMM: BM=128, BK=16, 256 threads ----------------
// lda: row stride of A. ACCUM (with !PARTIAL): C = [relu](acc + bias? + C_prev)
template <int BN, int TN, bool PARTIAL, bool RELU, bool ACCUM>
__global__ void gemm128(const float* __restrict__ A, const float* __restrict__ W,
                        const float* __restrict__ bias, float* __restrict__ C,
                        int K, int lda, int ldc, int kChunk, float* __restrict__ part) {
    const int N = gridDim.y * BN;
    __shared__ float As[16][132];
    __shared__ float Ws[16][BN];
    int tid = threadIdx.x;
    int tx = tid & 15, ty = tid >> 4;
    int row0 = blockIdx.x * 128;
    int col0 = blockIdx.y * BN;
    int k0 = blockIdx.z * kChunk;
    int k1 = k0 + kChunk;
    if (k1 > K) k1 = K;
    float acc[8][TN];
#pragma unroll
    for (int i = 0; i < 8; i++)
#pragma unroll
        for (int j = 0; j < TN; j++) acc[i][j] = 0.f;

    int ar = tid >> 2;
    int ak = (tid & 3) * 4;
    int wr = tid >> 4;
    int wc = (tid & 15) * (BN / 16);

    for (int kb = k0; kb < k1; kb += 16) {
        const float* Ap = A + (row0 + ar) * lda + kb + ak;
        float4 va = *(const float4*)Ap;
        float4 vb = *(const float4*)(Ap + 64 * lda);
        As[ak + 0][ar] = va.x; As[ak + 1][ar] = va.y;
        As[ak + 2][ar] = va.z; As[ak + 3][ar] = va.w;
        As[ak + 0][ar + 64] = vb.x; As[ak + 1][ar + 64] = vb.y;
        As[ak + 2][ar + 64] = vb.z; As[ak + 3][ar + 64] = vb.w;
        const float* Wp = W + (kb + wr) * N + col0 + wc;
        if (BN == 128) {
            *(float4*)&Ws[wr][wc] = *(const float4*)Wp;
            *(float4*)&Ws[wr][wc + 4] = *(const float4*)(Wp + 4);
        } else {
            *(float4*)&Ws[wr][wc] = *(const float4*)Wp;
        }
        __syncthreads();
#pragma unroll
        for (int kk = 0; kk < 16; kk++) {
            float av[8], bv[TN];
            *(float4*)&av[0] = *(const float4*)&As[kk][ty * 8];
            *(float4*)&av[4] = *(const float4*)&As[kk][ty * 8 + 4];
            *(float4*)&bv[0] = *(const float4*)&Ws[kk][tx * 4];
            if (TN == 8) *(float4*)&bv[4] = *(const float4*)&Ws[kk][64 + tx * 4];
#pragma unroll
            for (int i = 0; i < 8; i++)
#pragma unroll
                for (int j = 0; j < TN; j++) acc[i][j] += av[i] * bv[j];
        }
        __syncthreads();
    }

    if (PARTIAL) {
        const int Mtot = gridDim.x * 128;
        float* P = part + (size_t)blockIdx.z * Mtot * N;
#pragma unroll
        for (int i = 0; i < 8; i++) {
            int r = row0 + ty * 8 + i;
            *(float4*)&P[r * N + col0 + tx * 4] = *(float4*)&acc[i][0];
            if (TN == 8)
                *(float4*)&P[r * N + col0 + 64 + tx * 4] = *(float4*)&acc[i][4];
        }
    } else {
#pragma unroll
        for (int i = 0; i < 8; i++) {
            int r = row0 + ty * 8 + i;
#pragma unroll
            for (int h = 0; h < TN / 4; h++) {
                int c = col0 + h * 64 + tx * 4;
                float4 v;
                v.x = acc[i][h * 4 + 0] + (bias ? bias[c + 0] : 0.f);
                v.y = acc[i][h * 4 + 1] + (bias ? bias[c + 1] : 0.f);
                v.z = acc[i][h * 4 + 2] + (bias ? bias[c + 2] : 0.f);
                v.w = acc[i][h * 4 + 3] + (bias ? bias[c + 3] : 0.f);
                if (ACCUM) {
                    float4 prev = *(const float4*)&C[r * ldc + c];
                    v.x += prev.x; v.y += prev.y; v.z += prev.z; v.w += prev.w;
                }
                if (RELU) {
                    v.x = fmaxf(v.x, 0.f); v.y = fmaxf(v.y, 0.f);
                    v.z = fmaxf(v.z, 0.f); v.w = fmaxf(v.w, 0.f);
                }
                *(float4*)&C[r * ldc + c] = v;
            }
        }
    }
}

// reduce xt partials (16 splits, 1024x128) into g_xc[:,128:256] with both biases
__global__ void k_reduce_xt(const float* __restrict__ b_fcxt) {
    int idx4 = blockIdx.x * 256 + threadIdx.x;   // 32768 float4s
    int i = idx4 * 4;
    int b = i >> 7, col = i & 127;
    const float4* P = (const float4*)g_part;
    float4 s = P[idx4];
#pragma unroll
    for (int k = 1; k < 16; k++) f4add(s, P[k * (Bb * 128 / 4) + idx4]);
    float4 bs = *(const float4*)&g_bias2[col];
    float4 bf = *(const float4*)&b_fcxt[col];
    s.x += bs.x + bf.x; s.y += bs.y + bf.y;
    s.z += bs.z + bf.z; s.w += bs.w + bf.w;
    *(float4*)&g_xc[b * 256 + 128 + col] = s;
}

// ---------------- small GEMM for xd (M=1024,K=32,N=128) ----------------
__global__ void gemm_xd(const float* __restrict__ A, const float* __restrict__ W,
                        const float* __restrict__ bias, float* __restrict__ C) {
    __shared__ float As[64][33];
    __shared__ float Ws[32][128];
    int tid = threadIdx.x;
    int row0 = blockIdx.x * 64;
    for (int i = tid; i < 64 * 32; i += 256) As[i >> 5][i & 31] = A[row0 * 32 + i];
    for (int i = tid; i < 32 * 128; i += 256) Ws[i >> 7][i & 127] = W[i];
    __syncthreads();
    int tx = tid & 31, ty = tid >> 5;
    float acc[8][4];
#pragma unroll
    for (int i = 0; i < 8; i++)
#pragma unroll
        for (int m = 0; m < 4; m++) acc[i][m] = 0.f;
#pragma unroll
    for (int k = 0; k < 32; k++) {
        float rw[4];
#pragma unroll
        for (int m = 0; m < 4; m++) rw[m] = Ws[k][tx + 32 * m];
#pragma unroll
        for (int i = 0; i < 8; i++) {
            float ra = As[ty * 8 + i][k];
#pragma unroll
            for (int m = 0; m < 4; m++) acc[i][m] += ra * rw[m];
        }
    }
#pragma unroll
    for (int i = 0; i < 8; i++) {
        int r = row0 + ty * 8 + i;
#pragma unroll
        for (int m = 0; m < 4; m++) {
            int c = tx + 32 * m;
            C[r * 256 + c] = fmaxf(acc[i][m] + bias[c], 0.f);
        }
    }
}

// ---------------- final head ----------------
__global__ void k_out(const float* __restrict__ b_fc2, const float* __restrict__ wout,
                      const float* __restrict__ bout, float* __restrict__ out) {
    int b = blockIdx.x, c = threadIdx.x; // 256 threads
    float s = g_part[b * 256 + c];
#pragma unroll
    for (int k = 1; k < 4; k++) s += g_part[k * (Bb * 256) + b * 256 + c];
    float v = fmaxf(s + b_fc2[c], 0.f) * wout[c];
#pragma unroll
    for (int off = 16; off; off >>= 1) v += __shfl_down_sync(0xffffffffu, v, off);
    __shared__ float ps[8];
    if ((c & 31) == 0) ps[c >> 5] = v;
    __syncthreads();
    if (c == 0) {
        float t = bout[0];
#pragma unroll
        for (int q = 0; q < 8; q++) t += ps[q];
        out[b] = t;
    }
}

// ---------------- launcher ----------------
extern "C" void kernel_launch(void* const* d_in, const int* in_sizes, int n_in,
                              void* d_out, int out_size) {
    const float* x = (const float*)d_in[0];
    const int* edge_index = (const int*)d_in[1];
    const int* batch = (const int*)d_in[2];
    const int* target = (const int*)d_in[3];
    const float* w1a = (const float*)d_in[4];
    const float* b1a = (const float*)d_in[5];
    const float* w1b = (const float*)d_in[6];
    const float* b1b = (const float*)d_in[7];
    const float* wa = (const float*)d_in[8];
    const float* ba = (const float*)d_in[9];
    const float* wb = (const float*)d_in[10];
    const float* bb = (const float*)d_in[11];
    const float* gamma = (const float*)d_in[12];
    const float* beta = (const float*)d_in[13];
    const float* w_fcxd = (const float*)d_in[14];
    const float* b_fcxd = (const float*)d_in[15];
    const float* emb = (const float*)d_in[16];
    const float* conv_w = (const float*)d_in[17];
    const float* conv_b = (const float*)d_in[18];
    const float* w_fcxt = (const float*)d_in[19];
    const float* b_fcxt = (const float*)d_in[20];
    const float* w_fc1 = (const float*)d_in[21];
    const float* b_fc1 = (const float*)d_in[22];
    const float* w_fc2 = (const float*)d_in[23];
    const float* b_fc2 = (const float*)d_in[24];
    const float* w_out = (const float*)d_in[25];
    const float* b_out = (const float*)d_in[26];
    float* out = (float*)d_out;

    float *hgP, *xcP, *f1P, *AP, *UP, *partP;
    cudaGetSymbolAddress((void**)&hgP, g_hg);
    cudaGetSymbolAddress((void**)&xcP, g_xc);
    cudaGetSymbolAddress((void**)&f1P, g_f1);
    cudaGetSymbolAddress((void**)&AP, g_A);
    cudaGetSymbolAddress((void**)&UP, g_U);
    cudaGetSymbolAddress((void**)&partP, g_part);

    cudaFuncSetAttribute(k_buildA4, cudaFuncAttributeMaxDynamicSharedMemorySize,
                         4 * ADIM * (int)sizeof(float));

    // one-time streams (fork-join capture pattern)
    static cudaStream_t s2 = 0, s3 = 0;
    static cudaEvent_t evF = 0, evJ = 0, evC = 0;
    static bool tried = false;
    static bool use2 = false;
    if (!tried) {
        tried = true;
        if (cudaStreamCreateWithFlags(&s2, cudaStreamNonBlocking) == cudaSuccess &&
            cudaStreamCreateWithFlags(&s3, cudaStreamNonBlocking) == cudaSuccess &&
            cudaEventCreateWithFlags(&evF, cudaEventDisableTiming) == cudaSuccess &&
            cudaEventCreateWithFlags(&evJ, cudaEventDisableTiming) == cudaSuccess &&
            cudaEventCreateWithFlags(&evC, cudaEventDisableTiming) == cudaSuccess) {
            use2 = true;
        }
    }
    cudaStream_t st2 = use2 ? s2 : (cudaStream_t)0;
    cudaStream_t st3 = use2 ? s3 : (cudaStream_t)0;

    k_init<<<256, 256>>>();

    if (use2) {
        cudaEventRecord(evF, 0);
        cudaStreamWaitEvent(st2, evF, 0);
        cudaStreamWaitEvent(st3, evF, 0);
    }

    // ---- stream 3: privatized CSR build with hierarchical scan ----
    k_hist<<<Ee / 1024, 256, 0, st3>>>(edge_index);
    k_tot<<<64, 1024, 0, st3>>>();
    k_bscan<<<1, 32, 0, st3>>>();
    k_base<<<64, 1024, 0, st3>>>();
    k_fill<<<Ee / 1024, 256, 0, st3>>>(edge_index);
    if (use2) cudaEventRecord(evC, st3);

    // ---- stream 0: GIN chain ----
    k_proj78<<<Nn / 64, 256>>>(x, w1a);
    if (use2) cudaStreamWaitEvent(0, evC, 0);
    k_mlp<<<Nn / 64, 256>>>(0, b1a, w1b, b1b);
    for (int l = 0; l < 4; l++) {
        k_proj32<<<Nn / 64, 256>>>(l, gamma + l * 32, beta + l * 32, wa + l * 1024);
        k_mlp<<<Nn / 64, 256>>>(l + 1, ba + l * 32, wb + l * 1024, bb + l * 32);
    }
    k_pool<<<Nn / 256, 256>>>(batch, gamma + 128, beta + 128);
    gemm_xd<<<16, 256>>>(hgP, w_fcxd, b_fcxd, xcP);

    // ---- stream 2: protein branch + xt GEMM + fc1 xt-half (all hidden) ----
    k_transpose<<<NFIL, 256, 0, st2>>>(conv_w);
    k_buildA4<<<Bb / 4, 256, 4 * ADIM * sizeof(float), st2>>>(target);
    k_buildU<<<dim3(NFIL, VOCAB), 128, 0, st2>>>(emb, w_fcxt);
    k_bias2<<<NFIL, 128, 0, st2>>>(w_fcxt, conv_b);
    gemm128<128, 8, true, false, false><<<dim3(8, 1, 16), 256, 0, st2>>>(
        AP, UP, nullptr, nullptr, ADIM, ADIM, 0, 416, partP);
    k_reduce_xt<<<128, 256, 0, st2>>>(b_fcxt);
    // f1pre = xt @ w_fc1[128:256,:] + b_fc1  (no relu)
    gemm128<64, 4, false, false, false><<<dim3(8, 16, 1), 256, 0, st2>>>(
        xcP + 128, w_fc1 + 128 * 1024, b_fc1, f1P, 128, 256, 1024, 128, nullptr);

    if (use2) {
        cudaEventRecord(evJ, st2);
        cudaStreamWaitEvent(0, evJ, 0);
    }

    // ---- joint head: f1 = relu(xd @ w_fc1[0:128,:] + f1pre) ----
    gemm128<64, 4, false, true, true><<<dim3(8, 16, 1), 256>>>(
        xcP, w_fc1, nullptr, f1P, 128, 256, 1024, 128, nullptr);
    gemm128<64, 4, true, false, false><<<dim3(8, 4, 4), 256>>>(
        f1P, w_fc2, nullptr, nullptr, 1024, 1024, 0, 256, partP);
    k_out<<<Bb, 256>>>(b_fc2, w_out, b_out, out);
}